// round 3
// baseline (speedup 1.0000x reference)
#include <cuda_runtime.h>
#include <math.h>

#define BB 16
#define NN 256
#define DD 128
#define HH 8
#define HDIM 16
#define BN (BB*NN)          // 4096
#define EPSF 1e-8f
#define PI_F 3.14159265358979323846f
#define TWO_PI_F 6.28318530717958647692f
#define INV_TWO_PI_F 0.15915494309189533577f

// ---------------- scratch (device globals: allocation-guard safe) ----------------
__device__ float g_part[7*BN];                 // px,py,pz,e,pt,rap,phi  (SoA)
__device__ float g_bias[BB*HH*NN*NN];          // attn bias [b,h,i,j] (32MB)
__device__ float g_q[BN*DD];
__device__ float g_k[BN*DD];
__device__ float g_v[BN*DD];
__device__ float g_ao[BN*DD];

// ---------------- kernel 1: per-particle features ----------------
__global__ void k_part(const float* __restrict__ x_pf) {
    int idx = blockIdx.x * blockDim.x + threadIdx.x;
    if (idx >= BN) return;
    int b = idx >> 8;
    int n = idx & 255;
    const float* base = x_pf + b * 4 * NN + n;
    float px = base[0];
    float py = base[NN];
    float pz = base[2*NN];
    float e  = base[3*NN];
    float pt  = sqrtf(fmaxf(px*px + py*py, EPSF));
    float rap = 0.5f * log1pf(2.0f * pz / fmaxf(e - pz, 1e-20f));
    float phi = atan2f(py, px);
    g_part[0*BN + idx] = px;
    g_part[1*BN + idx] = py;
    g_part[2*BN + idx] = pz;
    g_part[3*BN + idx] = e;
    g_part[4*BN + idx] = pt;
    g_part[5*BN + idx] = rap;
    g_part[6*BN + idx] = phi;
}

// tanh-approximate GELU (matches jax.nn.gelu default approximate=True)
__device__ __forceinline__ float gelu_t(float x) {
    const float c = 0.7978845608028654f;
    float t = tanhf(c * fmaf(0.044715f * x, x * x, x));
    return 0.5f * x * (1.0f + t);
}

// ---------------- kernel 2: pairwise features + MLP -> attn bias ----------------
__global__ __launch_bounds__(256) void k_pair(
    const float* __restrict__ w0, const float* __restrict__ b0,
    const float* __restrict__ w1, const float* __restrict__ b1,
    const float* __restrict__ w2, const float* __restrict__ b2,
    const float* __restrict__ w3, const float* __restrict__ b3)
{
    __shared__ __align__(16) float sw0[4*64];
    __shared__ __align__(16) float sw1[64*64];
    __shared__ __align__(16) float sw2[64*64];
    __shared__ __align__(16) float sw3[64*8];
    __shared__ __align__(16) float sb0[64];
    __shared__ __align__(16) float sb1[64];
    __shared__ __align__(16) float sb2[64];
    __shared__ __align__(16) float sb3[8];

    int tid = threadIdx.x;
    for (int t = tid; t < 4*64;  t += 256) sw0[t] = w0[t];
    for (int t = tid; t < 64*64; t += 256) sw1[t] = w1[t];
    for (int t = tid; t < 64*64; t += 256) sw2[t] = w2[t];
    for (int t = tid; t < 64*8;  t += 256) sw3[t] = w3[t];
    if (tid < 64) { sb0[tid] = b0[tid]; sb1[tid] = b1[tid]; sb2[tid] = b2[tid]; }
    if (tid < 8)  { sb3[tid] = b3[tid]; }
    __syncthreads();

    int p = blockIdx.x * 256 + tid;
    int b = p >> 16;
    int i = (p >> 8) & 255;
    int j = p & 255;
    int bi = (b << 8) + i;
    int bj = (b << 8) + j;

    float pxi = g_part[0*BN + bi], pxj = g_part[0*BN + bj];
    float pyi = g_part[1*BN + bi], pyj = g_part[1*BN + bj];
    float pzi = g_part[2*BN + bi], pzj = g_part[2*BN + bj];
    float ei  = g_part[3*BN + bi], ej  = g_part[3*BN + bj];
    float pti = g_part[4*BN + bi], ptj = g_part[4*BN + bj];
    float rpi = g_part[5*BN + bi], rpj = g_part[5*BN + bj];
    float phi_i = g_part[6*BN + bi], phi_j = g_part[6*BN + bj];

    float drap = rpi - rpj;
    float dw = phi_i - phi_j + PI_F;
    dw -= floorf(dw * INV_TWO_PI_F) * TWO_PI_F;     // floor-mod into [0, 2pi)
    float dphi = dw - PI_F;
    float delta = sqrtf(drap*drap + dphi*dphi);
    float lndelta = logf(fmaxf(delta, EPSF));
    float ptmin = fminf(pti, ptj);
    float lnkt = logf(fmaxf(ptmin * delta, EPSF));
    float lnz  = logf(fmaxf(ptmin / fmaxf(pti + ptj, EPSF), EPSF));
    float es = ei + ej, xs = pxi + pxj, ys = pyi + pyj, zs = pzi + pzj;
    float lnm2 = logf(fmaxf(es*es - xs*xs - ys*ys - zs*zs, EPSF));

    float f0 = lnkt, f1 = lnz, f2 = lndelta, f3 = lnm2;

    float ha[64], hb[64];

    // layer 0: 4 -> 64
    #pragma unroll
    for (int k = 0; k < 64; k += 4) {
        float4 a = *(const float4*)&sb0[k];
        float4 w;
        w = *(const float4*)&sw0[0*64 + k];
        a.x = fmaf(f0, w.x, a.x); a.y = fmaf(f0, w.y, a.y); a.z = fmaf(f0, w.z, a.z); a.w = fmaf(f0, w.w, a.w);
        w = *(const float4*)&sw0[1*64 + k];
        a.x = fmaf(f1, w.x, a.x); a.y = fmaf(f1, w.y, a.y); a.z = fmaf(f1, w.z, a.z); a.w = fmaf(f1, w.w, a.w);
        w = *(const float4*)&sw0[2*64 + k];
        a.x = fmaf(f2, w.x, a.x); a.y = fmaf(f2, w.y, a.y); a.z = fmaf(f2, w.z, a.z); a.w = fmaf(f2, w.w, a.w);
        w = *(const float4*)&sw0[3*64 + k];
        a.x = fmaf(f3, w.x, a.x); a.y = fmaf(f3, w.y, a.y); a.z = fmaf(f3, w.z, a.z); a.w = fmaf(f3, w.w, a.w);
        ha[k+0] = gelu_t(a.x); ha[k+1] = gelu_t(a.y); ha[k+2] = gelu_t(a.z); ha[k+3] = gelu_t(a.w);
    }

    // layer 1: 64 -> 64
    #pragma unroll
    for (int k = 0; k < 64; k += 4) {
        float4 a = *(const float4*)&sb1[k];
        #pragma unroll
        for (int in = 0; in < 64; in++) {
            float4 w = *(const float4*)&sw1[in*64 + k];
            float h = ha[in];
            a.x = fmaf(h, w.x, a.x); a.y = fmaf(h, w.y, a.y);
            a.z = fmaf(h, w.z, a.z); a.w = fmaf(h, w.w, a.w);
        }
        hb[k+0] = gelu_t(a.x); hb[k+1] = gelu_t(a.y); hb[k+2] = gelu_t(a.z); hb[k+3] = gelu_t(a.w);
    }

    // layer 2: 64 -> 64
    #pragma unroll
    for (int k = 0; k < 64; k += 4) {
        float4 a = *(const float4*)&sb2[k];
        #pragma unroll
        for (int in = 0; in < 64; in++) {
            float4 w = *(const float4*)&sw2[in*64 + k];
            float h = hb[in];
            a.x = fmaf(h, w.x, a.x); a.y = fmaf(h, w.y, a.y);
            a.z = fmaf(h, w.z, a.z); a.w = fmaf(h, w.w, a.w);
        }
        ha[k+0] = gelu_t(a.x); ha[k+1] = gelu_t(a.y); ha[k+2] = gelu_t(a.z); ha[k+3] = gelu_t(a.w);
    }

    // layer 3: 64 -> 8 (no activation)  -> write transposed to [b,h,i,j]
    float outv[8];
    #pragma unroll
    for (int k = 0; k < 8; k += 4) {
        float4 a = *(const float4*)&sb3[k];
        #pragma unroll
        for (int in = 0; in < 64; in++) {
            float4 w = *(const float4*)&sw3[in*8 + k];
            float h = ha[in];
            a.x = fmaf(h, w.x, a.x); a.y = fmaf(h, w.y, a.y);
            a.z = fmaf(h, w.z, a.z); a.w = fmaf(h, w.w, a.w);
        }
        outv[k+0] = a.x; outv[k+1] = a.y; outv[k+2] = a.z; outv[k+3] = a.w;
    }

    float* bp = g_bias + ((b * HH) * NN + i) * NN + j;
    #pragma unroll
    for (int k = 0; k < 8; k++) bp[k * NN * NN] = outv[k];
}

// ---------------- kernel 3: QKV projections ----------------
__global__ __launch_bounds__(128) void k_qkv(
    const float* __restrict__ xf,
    const float* __restrict__ wq, const float* __restrict__ wk, const float* __restrict__ wv,
    const float* __restrict__ bq, const float* __restrict__ bk, const float* __restrict__ bv)
{
    __shared__ float xs[16][128];
    int tid = threadIdx.x;
    int r0 = blockIdx.x * 16;
    for (int t = tid; t < 16*128; t += 128) xs[t >> 7][t & 127] = xf[r0*128 + t];
    __syncthreads();

    int d = tid;
    float aq[16], ak[16], av[16];
    float bqv = bq[d], bkv = bk[d], bvv = bv[d];
    #pragma unroll
    for (int r = 0; r < 16; r++) { aq[r] = bqv; ak[r] = bkv; av[r] = bvv; }

    #pragma unroll 4
    for (int k = 0; k < 128; k++) {
        float wqv = wq[k*128 + d];
        float wkv = wk[k*128 + d];
        float wvv = wv[k*128 + d];
        #pragma unroll
        for (int r = 0; r < 16; r++) {
            float x = xs[r][k];
            aq[r] = fmaf(x, wqv, aq[r]);
            ak[r] = fmaf(x, wkv, ak[r]);
            av[r] = fmaf(x, wvv, av[r]);
        }
    }
    #pragma unroll
    for (int r = 0; r < 16; r++) {
        int row = r0 + r;
        g_q[row*128 + d] = aq[r];
        g_k[row*128 + d] = ak[r];
        g_v[row*128 + d] = av[r];
    }
}

// ---------------- kernel 4: attention (per (b,h), 8 i-rows per block) ----------------
__global__ __launch_bounds__(256) void k_attn() {
    int bid = blockIdx.x;
    int it = bid & 31;
    int h  = (bid >> 5) & 7;
    int b  = bid >> 8;

    __shared__ float ks[256][17];
    __shared__ float vs[256][17];
    __shared__ float ps[8][256];

    int tid = threadIdx.x;
    // cooperative K/V tile load: thread = one j row
    {
        int j = tid;
        const float* kp = g_k + (b*256 + j)*128 + h*16;
        const float* vp = g_v + (b*256 + j)*128 + h*16;
        #pragma unroll
        for (int d = 0; d < 16; d += 4) {
            float4 kv = *(const float4*)&kp[d];
            float4 vv = *(const float4*)&vp[d];
            ks[j][d+0] = kv.x; ks[j][d+1] = kv.y; ks[j][d+2] = kv.z; ks[j][d+3] = kv.w;
            vs[j][d+0] = vv.x; vs[j][d+1] = vv.y; vs[j][d+2] = vv.z; vs[j][d+3] = vv.w;
        }
    }
    __syncthreads();

    int w = tid >> 5;
    int lane = tid & 31;
    int i = it * 8 + w;

    float q[16];
    const float* qp = g_q + (b*256 + i)*128 + h*16;
    #pragma unroll
    for (int d = 0; d < 16; d++) q[d] = qp[d];

    const float* bp = g_bias + ((b*8 + h)*256 + i)*256;

    float s[8];
    float m = -1e30f;
    #pragma unroll
    for (int jj = 0; jj < 8; jj++) {
        int j = jj*32 + lane;
        float acc = 0.0f;
        #pragma unroll
        for (int d = 0; d < 16; d++) acc = fmaf(q[d], ks[j][d], acc);
        s[jj] = acc * 0.25f + bp[j];           // 1/sqrt(16) = 0.25
        m = fmaxf(m, s[jj]);
    }
    #pragma unroll
    for (int off = 16; off >= 1; off >>= 1) m = fmaxf(m, __shfl_xor_sync(0xffffffffu, m, off));

    float sum = 0.0f;
    #pragma unroll
    for (int jj = 0; jj < 8; jj++) { s[jj] = __expf(s[jj] - m); sum += s[jj]; }
    #pragma unroll
    for (int off = 16; off >= 1; off >>= 1) sum += __shfl_xor_sync(0xffffffffu, sum, off);
    float inv = 1.0f / sum;

    #pragma unroll
    for (int jj = 0; jj < 8; jj++) ps[w][jj*32 + lane] = s[jj] * inv;
    __syncwarp();

    if (lane < 16) {
        int d = lane;
        float acc = 0.0f;
        #pragma unroll 4
        for (int j = 0; j < 256; j++) acc = fmaf(ps[w][j], vs[j][d], acc);
        g_ao[(b*256 + i)*128 + h*16 + d] = acc;
    }
}

// ---------------- kernel 5: output projection ----------------
__global__ __launch_bounds__(128) void k_outproj(
    const float* __restrict__ wo, const float* __restrict__ bo, float* __restrict__ out)
{
    __shared__ float xs[16][128];
    int tid = threadIdx.x;
    int r0 = blockIdx.x * 16;
    for (int t = tid; t < 16*128; t += 128) xs[t >> 7][t & 127] = g_ao[r0*128 + t];
    __syncthreads();

    int d = tid;
    float acc[16];
    float bv = bo[d];
    #pragma unroll
    for (int r = 0; r < 16; r++) acc[r] = bv;

    #pragma unroll 4
    for (int k = 0; k < 128; k++) {
        float wv = wo[k*128 + d];
        #pragma unroll
        for (int r = 0; r < 16; r++) acc[r] = fmaf(xs[r][k], wv, acc[r]);
    }
    #pragma unroll
    for (int r = 0; r < 16; r++) out[(r0 + r)*128 + d] = acc[r];
}

// ---------------- launch ----------------
extern "C" void kernel_launch(void* const* d_in, const int* in_sizes, int n_in,
                              void* d_out, int out_size) {
    (void)in_sizes; (void)n_in; (void)out_size;
    const float* x_pf   = (const float*)d_in[0];
    const float* x_feat = (const float*)d_in[1];
    const float* w0 = (const float*)d_in[2];
    const float* b0 = (const float*)d_in[3];
    const float* w1 = (const float*)d_in[4];
    const float* b1 = (const float*)d_in[5];
    const float* w2 = (const float*)d_in[6];
    const float* b2 = (const float*)d_in[7];
    const float* w3 = (const float*)d_in[8];
    const float* b3 = (const float*)d_in[9];
    const float* wq = (const float*)d_in[10];
    const float* wk = (const float*)d_in[11];
    const float* wv = (const float*)d_in[12];
    const float* wo = (const float*)d_in[13];
    const float* bq = (const float*)d_in[14];
    const float* bk = (const float*)d_in[15];
    const float* bv = (const float*)d_in[16];
    const float* bo = (const float*)d_in[17];

    k_part<<<16, 256>>>(x_pf);
    k_pair<<<4096, 256>>>(w0, b0, w1, b1, w2, b2, w3, b3);
    k_qkv<<<256, 128>>>(x_feat, wq, wk, wv, bq, bk, bv);
    k_attn<<<4096, 256>>>();
    k_outproj<<<256, 128>>>(wo, bo, (float*)d_out);
}

// round 5
// speedup vs baseline: 1.8636x; 1.8636x over previous
#include <cuda_runtime.h>
#include <math.h>

#define BB 16
#define NN 256
#define DD 128
#define HH 8
#define HDIM 16
#define BN (BB*NN)          // 4096
#define EPSF 1e-8f
#define PI_F 3.14159265358979323846f
#define TWO_PI_F 6.28318530717958647692f
#define INV_TWO_PI_F 0.15915494309189533577f
#define NTILE 16            // 256/16 i,j tiles
#define NTP 136             // upper-triangle tile pairs: 16*17/2

// ---------------- scratch (device globals: allocation-guard safe) ----------------
__device__ float g_part[7*BN];                 // px,py,pz,e,pt,rap,phi  (SoA)
__device__ float g_bias[BB*HH*NN*NN];          // attn bias [b,h,i,j] (32MB)
__device__ float g_q[BN*DD];
__device__ float g_k[BN*DD];
__device__ float g_v[BN*DD];
__device__ float g_ao[BN*DD];

// ---------------- kernel 1: per-particle features ----------------
__global__ void k_part(const float* __restrict__ x_pf) {
    int idx = blockIdx.x * blockDim.x + threadIdx.x;
    if (idx >= BN) return;
    int b = idx >> 8;
    int n = idx & 255;
    const float* base = x_pf + b * 4 * NN + n;
    float px = base[0];
    float py = base[NN];
    float pz = base[2*NN];
    float e  = base[3*NN];
    float pt  = sqrtf(fmaxf(px*px + py*py, EPSF));
    float rap = 0.5f * log1pf(2.0f * pz / fmaxf(e - pz, 1e-20f));
    float phi = atan2f(py, px);
    g_part[0*BN + idx] = px;
    g_part[1*BN + idx] = py;
    g_part[2*BN + idx] = pz;
    g_part[3*BN + idx] = e;
    g_part[4*BN + idx] = pt;
    g_part[5*BN + idx] = rap;
    g_part[6*BN + idx] = phi;
}

// fast tanh-approximate GELU: gelu(x) = x * sigmoid(2c*(x + 0.044715 x^3))
// __expf + __fdividef: ~1e-6 rel err; all large-|x| limits -> correct 0 / x.
__device__ __forceinline__ float gelu_t(float x) {
    const float c2 = 1.5957691216057308f;   // 2 * sqrt(2/pi)
    float u = c2 * fmaf(0.044715f * x, x * x, x);
    return __fdividef(x, 1.0f + __expf(-u));
}

// ---------------- kernel 2: pairwise features + MLP -> attn bias ----------------
// Symmetric: bias[b,h,i,j] == bias[b,h,j,i]. Compute only upper-triangle
// 16x16 tiles (136 of 256), mirror-write via SMEM transpose.
__global__ __launch_bounds__(256) void k_pair(
    const float* __restrict__ w0, const float* __restrict__ b0,
    const float* __restrict__ w1, const float* __restrict__ b1,
    const float* __restrict__ w2, const float* __restrict__ b2,
    const float* __restrict__ w3, const float* __restrict__ b3)
{
    __shared__ __align__(16) float sw0[4*64];
    __shared__ __align__(16) float sw1[64*64];
    __shared__ __align__(16) float sw2[64*64];
    __shared__ __align__(16) float sw3[64*8];
    __shared__ __align__(16) float sb0[64];
    __shared__ __align__(16) float sb1[64];
    __shared__ __align__(16) float sb2[64];
    __shared__ __align__(16) float sb3[8];
    __shared__ __align__(16) float st[8][16][24];  // [h][jl][il] staging for mirror

    int tid = threadIdx.x;
    for (int t = tid; t < 4*64;  t += 256) sw0[t] = w0[t];
    for (int t = tid; t < 64*64; t += 256) sw1[t] = w1[t];
    for (int t = tid; t < 64*64; t += 256) sw2[t] = w2[t];
    for (int t = tid; t < 64*8;  t += 256) sw3[t] = w3[t];
    if (tid < 64) { sb0[tid] = b0[tid]; sb1[tid] = b1[tid]; sb2[tid] = b2[tid]; }
    if (tid < 8)  { sb3[tid] = b3[tid]; }
    __syncthreads();

    int b  = blockIdx.x / NTP;
    int tp = blockIdx.x - b * NTP;
    // decode upper-triangle tile pair (ti <= tj)
    int ti = 0, rem = tp;
    while (rem >= NTILE - ti) { rem -= NTILE - ti; ti++; }
    int tj = ti + rem;

    int il = tid >> 4;         // 0..15
    int jl = tid & 15;         // 0..15
    int i = ti * 16 + il;
    int j = tj * 16 + jl;
    int bi = (b << 8) + i;
    int bj = (b << 8) + j;

    float pxi = g_part[0*BN + bi], pxj = g_part[0*BN + bj];
    float pyi = g_part[1*BN + bi], pyj = g_part[1*BN + bj];
    float pzi = g_part[2*BN + bi], pzj = g_part[2*BN + bj];
    float ei  = g_part[3*BN + bi], ej  = g_part[3*BN + bj];
    float pti = g_part[4*BN + bi], ptj = g_part[4*BN + bj];
    float rpi = g_part[5*BN + bi], rpj = g_part[5*BN + bj];
    float phi_i = g_part[6*BN + bi], phi_j = g_part[6*BN + bj];

    float drap = rpi - rpj;
    float dw = phi_i - phi_j + PI_F;
    dw -= floorf(dw * INV_TWO_PI_F) * TWO_PI_F;     // floor-mod into [0, 2pi)
    float dphi = dw - PI_F;
    float delta = sqrtf(drap*drap + dphi*dphi);
    float lndelta = __logf(fmaxf(delta, EPSF));
    float ptmin = fminf(pti, ptj);
    float lnkt = __logf(fmaxf(ptmin * delta, EPSF));
    float lnz  = __logf(fmaxf(__fdividef(ptmin, fmaxf(pti + ptj, EPSF)), EPSF));
    float es = ei + ej, xs = pxi + pxj, ys = pyi + pyj, zs = pzi + pzj;
    float lnm2 = __logf(fmaxf(es*es - xs*xs - ys*ys - zs*zs, EPSF));

    float f0 = lnkt, f1 = lnz, f2 = lndelta, f3 = lnm2;

    float ha[64], hb[64];

    // layer 0: 4 -> 64
    #pragma unroll
    for (int k = 0; k < 64; k += 4) {
        float4 a = *(const float4*)&sb0[k];
        float4 w;
        w = *(const float4*)&sw0[0*64 + k];
        a.x = fmaf(f0, w.x, a.x); a.y = fmaf(f0, w.y, a.y); a.z = fmaf(f0, w.z, a.z); a.w = fmaf(f0, w.w, a.w);
        w = *(const float4*)&sw0[1*64 + k];
        a.x = fmaf(f1, w.x, a.x); a.y = fmaf(f1, w.y, a.y); a.z = fmaf(f1, w.z, a.z); a.w = fmaf(f1, w.w, a.w);
        w = *(const float4*)&sw0[2*64 + k];
        a.x = fmaf(f2, w.x, a.x); a.y = fmaf(f2, w.y, a.y); a.z = fmaf(f2, w.z, a.z); a.w = fmaf(f2, w.w, a.w);
        w = *(const float4*)&sw0[3*64 + k];
        a.x = fmaf(f3, w.x, a.x); a.y = fmaf(f3, w.y, a.y); a.z = fmaf(f3, w.z, a.z); a.w = fmaf(f3, w.w, a.w);
        ha[k+0] = gelu_t(a.x); ha[k+1] = gelu_t(a.y); ha[k+2] = gelu_t(a.z); ha[k+3] = gelu_t(a.w);
    }

    // layer 1: 64 -> 64
    #pragma unroll
    for (int k = 0; k < 64; k += 4) {
        float4 a = *(const float4*)&sb1[k];
        #pragma unroll
        for (int in = 0; in < 64; in++) {
            float4 w = *(const float4*)&sw1[in*64 + k];
            float h = ha[in];
            a.x = fmaf(h, w.x, a.x); a.y = fmaf(h, w.y, a.y);
            a.z = fmaf(h, w.z, a.z); a.w = fmaf(h, w.w, a.w);
        }
        hb[k+0] = gelu_t(a.x); hb[k+1] = gelu_t(a.y); hb[k+2] = gelu_t(a.z); hb[k+3] = gelu_t(a.w);
    }

    // layer 2: 64 -> 64
    #pragma unroll
    for (int k = 0; k < 64; k += 4) {
        float4 a = *(const float4*)&sb2[k];
        #pragma unroll
        for (int in = 0; in < 64; in++) {
            float4 w = *(const float4*)&sw2[in*64 + k];
            float h = hb[in];
            a.x = fmaf(h, w.x, a.x); a.y = fmaf(h, w.y, a.y);
            a.z = fmaf(h, w.z, a.z); a.w = fmaf(h, w.w, a.w);
        }
        ha[k+0] = gelu_t(a.x); ha[k+1] = gelu_t(a.y); ha[k+2] = gelu_t(a.z); ha[k+3] = gelu_t(a.w);
    }

    // layer 3: 64 -> 8 (no activation)
    float outv[8];
    #pragma unroll
    for (int k = 0; k < 8; k += 4) {
        float4 a = *(const float4*)&sb3[k];
        #pragma unroll
        for (int in = 0; in < 64; in++) {
            float4 w = *(const float4*)&sw3[in*8 + k];
            float h = ha[in];
            a.x = fmaf(h, w.x, a.x); a.y = fmaf(h, w.y, a.y);
            a.z = fmaf(h, w.z, a.z); a.w = fmaf(h, w.w, a.w);
        }
        outv[k+0] = a.x; outv[k+1] = a.y; outv[k+2] = a.z; outv[k+3] = a.w;
    }

    // direct write [b,h,i,j] (rows coalesced per warp)
    #pragma unroll
    for (int h = 0; h < 8; h++)
        g_bias[(((b*8 + h)*256 + i))*256 + j] = outv[h];

    // mirror write [b,h,j,i] via SMEM transpose (coalesced float4 stores)
    #pragma unroll
    for (int h = 0; h < 8; h++) st[h][jl][il] = outv[h];
    __syncthreads();
    {
        int h   = tid >> 5;          // 0..7
        int r   = tid & 31;
        int jl2 = r & 15;            // 0..15
        int ih  = r >> 4;            // 0..1
        int jrow = tj*16 + jl2;
        int icol = ti*16 + ih*8;
        float4 v0 = *(const float4*)&st[h][jl2][ih*8 + 0];
        float4 v1 = *(const float4*)&st[h][jl2][ih*8 + 4];
        float* q = g_bias + (((b*8 + h)*256 + jrow))*256 + icol;
        *(float4*)&q[0] = v0;
        *(float4*)&q[4] = v1;
    }
}

// ---------------- kernel 3: QKV projections ----------------
__global__ __launch_bounds__(128) void k_qkv(
    const float* __restrict__ xf,
    const float* __restrict__ wq, const float* __restrict__ wk, const float* __restrict__ wv,
    const float* __restrict__ bq, const float* __restrict__ bk, const float* __restrict__ bv)
{
    __shared__ float xs[16][128];
    int tid = threadIdx.x;
    int r0 = blockIdx.x * 16;
    for (int t = tid; t < 16*128; t += 128) xs[t >> 7][t & 127] = xf[r0*128 + t];
    __syncthreads();

    int d = tid;
    float aq[16], ak[16], av[16];
    float bqv = bq[d], bkv = bk[d], bvv = bv[d];
    #pragma unroll
    for (int r = 0; r < 16; r++) { aq[r] = bqv; ak[r] = bkv; av[r] = bvv; }

    #pragma unroll 4
    for (int k = 0; k < 128; k++) {
        float wqv = wq[k*128 + d];
        float wkv = wk[k*128 + d];
        float wvv = wv[k*128 + d];
        #pragma unroll
        for (int r = 0; r < 16; r++) {
            float x = xs[r][k];
            aq[r] = fmaf(x, wqv, aq[r]);
            ak[r] = fmaf(x, wkv, ak[r]);
            av[r] = fmaf(x, wvv, av[r]);
        }
    }
    #pragma unroll
    for (int r = 0; r < 16; r++) {
        int row = r0 + r;
        g_q[row*128 + d] = aq[r];
        g_k[row*128 + d] = ak[r];
        g_v[row*128 + d] = av[r];
    }
}

// ---------------- kernel 4: attention (per (b,h), 8 i-rows per block) ----------------
__global__ __launch_bounds__(256) void k_attn() {
    int bid = blockIdx.x;
    int it = bid & 31;
    int h  = (bid >> 5) & 7;
    int b  = bid >> 8;

    __shared__ float ks[256][17];
    __shared__ float vs[256][17];
    __shared__ float ps[8][256];

    int tid = threadIdx.x;
    {
        int j = tid;
        const float* kp = g_k + (b*256 + j)*128 + h*16;
        const float* vp = g_v + (b*256 + j)*128 + h*16;
        #pragma unroll
        for (int d = 0; d < 16; d += 4) {
            float4 kv = *(const float4*)&kp[d];
            float4 vv = *(const float4*)&vp[d];
            ks[j][d+0] = kv.x; ks[j][d+1] = kv.y; ks[j][d+2] = kv.z; ks[j][d+3] = kv.w;
            vs[j][d+0] = vv.x; vs[j][d+1] = vv.y; vs[j][d+2] = vv.z; vs[j][d+3] = vv.w;
        }
    }
    __syncthreads();

    int w = tid >> 5;
    int lane = tid & 31;
    int i = it * 8 + w;

    float q[16];
    const float* qp = g_q + (b*256 + i)*128 + h*16;
    #pragma unroll
    for (int d = 0; d < 16; d++) q[d] = qp[d];

    const float* bp = g_bias + ((b*8 + h)*256 + i)*256;

    float s[8];
    float m = -1e30f;
    #pragma unroll
    for (int jj = 0; jj < 8; jj++) {
        int j = jj*32 + lane;
        float acc = 0.0f;
        #pragma unroll
        for (int d = 0; d < 16; d++) acc = fmaf(q[d], ks[j][d], acc);
        s[jj] = acc * 0.25f + bp[j];           // 1/sqrt(16) = 0.25
        m = fmaxf(m, s[jj]);
    }
    #pragma unroll
    for (int off = 16; off >= 1; off >>= 1) m = fmaxf(m, __shfl_xor_sync(0xffffffffu, m, off));

    float sum = 0.0f;
    #pragma unroll
    for (int jj = 0; jj < 8; jj++) { s[jj] = __expf(s[jj] - m); sum += s[jj]; }
    #pragma unroll
    for (int off = 16; off >= 1; off >>= 1) sum += __shfl_xor_sync(0xffffffffu, sum, off);
    float inv = __fdividef(1.0f, sum);

    #pragma unroll
    for (int jj = 0; jj < 8; jj++) ps[w][jj*32 + lane] = s[jj] * inv;
    __syncwarp();

    // PV: full warp — lane = (parity, d); even/odd j split, shuffle combine
    {
        int d   = lane & 15;
        int par = lane >> 4;
        float acc = 0.0f;
        #pragma unroll 4
        for (int jj = 0; jj < 128; jj++) {
            int j = 2*jj + par;
            acc = fmaf(ps[w][j], vs[j][d], acc);
        }
        acc += __shfl_xor_sync(0xffffffffu, acc, 16);
        if (lane < 16)
            g_ao[(b*256 + i)*128 + h*16 + d] = acc;
    }
}

// ---------------- kernel 5: output projection ----------------
__global__ __launch_bounds__(128) void k_outproj(
    const float* __restrict__ wo, const float* __restrict__ bo, float* __restrict__ out)
{
    __shared__ float xs[16][128];
    int tid = threadIdx.x;
    int r0 = blockIdx.x * 16;
    for (int t = tid; t < 16*128; t += 128) xs[t >> 7][t & 127] = g_ao[r0*128 + t];
    __syncthreads();

    int d = tid;
    float acc[16];
    float bv = bo[d];
    #pragma unroll
    for (int r = 0; r < 16; r++) acc[r] = bv;

    #pragma unroll 4
    for (int k = 0; k < 128; k++) {
        float wv = wo[k*128 + d];
        #pragma unroll
        for (int r = 0; r < 16; r++) acc[r] = fmaf(xs[r][k], wv, acc[r]);
    }
    #pragma unroll
    for (int r = 0; r < 16; r++) out[(r0 + r)*128 + d] = acc[r];
}

// ---------------- launch ----------------
extern "C" void kernel_launch(void* const* d_in, const int* in_sizes, int n_in,
                              void* d_out, int out_size) {
    (void)in_sizes; (void)n_in; (void)out_size;
    const float* x_pf   = (const float*)d_in[0];
    const float* x_feat = (const float*)d_in[1];
    const float* w0 = (const float*)d_in[2];
    const float* b0 = (const float*)d_in[3];
    const float* w1 = (const float*)d_in[4];
    const float* b1 = (const float*)d_in[5];
    const float* w2 = (const float*)d_in[6];
    const float* b2 = (const float*)d_in[7];
    const float* w3 = (const float*)d_in[8];
    const float* b3 = (const float*)d_in[9];
    const float* wq = (const float*)d_in[10];
    const float* wk = (const float*)d_in[11];
    const float* wv = (const float*)d_in[12];
    const float* wo = (const float*)d_in[13];
    const float* bq = (const float*)d_in[14];
    const float* bk = (const float*)d_in[15];
    const float* bv = (const float*)d_in[16];
    const float* bo = (const float*)d_in[17];

    k_part<<<16, 256>>>(x_pf);
    k_pair<<<BB*NTP, 256>>>(w0, b0, w1, b1, w2, b2, w3, b3);
    k_qkv<<<256, 128>>>(x_feat, wq, wk, wv, bq, bk, bv);
    k_attn<<<4096, 256>>>();
    k_outproj<<<256, 128>>>(wo, bo, (float*)d_out);
}

// round 11
// speedup vs baseline: 4.2129x; 2.2607x over previous
#include <cuda_runtime.h>
#include <cuda_fp16.h>
#include <mma.h>
#include <math.h>
#include <stdint.h>

using namespace nvcuda;

#define BB 16
#define NN 256
#define DD 128
#define HH 8
#define HDIM 16
#define BN (BB*NN)          // 4096
#define EPSF 1e-8f
#define PI_F 3.14159265358979323846f
#define TWO_PI_F 6.28318530717958647692f
#define INV_TWO_PI_F 0.15915494309189533577f
#define NTILE 16
#define NTP 136             // upper-triangle tile pairs 16*17/2

#define ASTR 72             // A row stride in halves (144B)
#define BSTR 72             // B row stride in halves

// ---- dynamic SMEM layout (bytes) ----
#define SM_AH   0                      // 128*72*2 = 18432
#define SM_AL   18432                  // 18432
#define SM_B1H  36864                  // 9216
#define SM_B1L  46080                  // 9216
#define SM_B2H  55296                  // 9216
#define SM_B2L  64512                  // 9216
#define SM_B3H  73728                  // 2048
#define SM_B3L  75776                  // 2048
#define SM_SCR  77824                  // 4*16*20*4 = 5120
#define SM_W0   82944                  // 1024
#define SM_SB0  83968                  // 256
#define SM_SB1  84224                  // 256
#define SM_SB2  84480                  // 256
#define SM_SB3  84736                  // 64
#define SM_TOT  84800

// ---------------- scratch ----------------
__device__ float g_part[7*BN];
__device__ float g_bias[BB*HH*NN*NN];
__device__ float g_q[BN*DD];
__device__ float g_k[BN*DD];
__device__ float g_v[BN*DD];
__device__ float g_ao[BN*DD];

// ---------------- kernel 1: per-particle features ----------------
__global__ void k_part(const float* __restrict__ x_pf) {
    int idx = blockIdx.x * blockDim.x + threadIdx.x;
    if (idx >= BN) return;
    int b = idx >> 8;
    int n = idx & 255;
    const float* base = x_pf + b * 4 * NN + n;
    float px = base[0];
    float py = base[NN];
    float pz = base[2*NN];
    float e  = base[3*NN];
    float pt  = sqrtf(fmaxf(px*px + py*py, EPSF));
    float rap = 0.5f * log1pf(2.0f * pz / fmaxf(e - pz, 1e-20f));
    float phi = atan2f(py, px);
    g_part[0*BN + idx] = px;
    g_part[1*BN + idx] = py;
    g_part[2*BN + idx] = pz;
    g_part[3*BN + idx] = e;
    g_part[4*BN + idx] = pt;
    g_part[5*BN + idx] = rap;
    g_part[6*BN + idx] = phi;
}

// fast tanh-approximate GELU (matches jax.nn.gelu approximate)
__device__ __forceinline__ float gelu_t(float x) {
    const float c2 = 1.5957691216057308f;   // 2*sqrt(2/pi)
    float u = c2 * fmaf(0.044715f * x, x * x, x);
    return __fdividef(x, 1.0f + __expf(-u));
}

// split a float into hi/lo fp16 pair
__device__ __forceinline__ void split_h(float a, __half& hi, __half& lo) {
    hi = __float2half_rn(a);
    lo = __float2half_rn(a - __half2float(hi));
}

// pack 8 floats into hi uint4 + lo uint4
__device__ __forceinline__ void pack8(const float* v, uint4& ph, uint4& pl) {
    __half h0, l0, h1, l1;
    uint32_t* phu = (uint32_t*)&ph;
    uint32_t* plu = (uint32_t*)&pl;
    #pragma unroll
    for (int q = 0; q < 4; q++) {
        split_h(v[2*q+0], h0, l0);
        split_h(v[2*q+1], h1, l1);
        __half2 hh = __halves2half2(h0, h1);
        __half2 ll = __halves2half2(l0, l1);
        phu[q] = *(uint32_t*)&hh;
        plu[q] = *(uint32_t*)&ll;
    }
}

// ---------------- kernel 2: pair MLP via split fp16 wmma (fp32-accurate) ----------------
// Block = 128 threads = 128 pairs. 4 warps, each owns a 32-row M-slab.
// D = Ah*Bh + Ah*Bl + Al*Bh  (error ~2^-22). Layers run in place, per-warp.
__global__ __launch_bounds__(128) void k_pair(
    const float* __restrict__ w0, const float* __restrict__ b0,
    const float* __restrict__ w1, const float* __restrict__ b1,
    const float* __restrict__ w2, const float* __restrict__ b2,
    const float* __restrict__ w3, const float* __restrict__ b3)
{
    extern __shared__ __align__(16) unsigned char sm[];
    __half* sAh = (__half*)(sm + SM_AH);
    __half* sAl = (__half*)(sm + SM_AL);
    float* sw0 = (float*)(sm + SM_W0);
    float* sb0 = (float*)(sm + SM_SB0);
    float* sb1 = (float*)(sm + SM_SB1);
    float* sb2 = (float*)(sm + SM_SB2);
    float* sb3 = (float*)(sm + SM_SB3);

    int tid = threadIdx.x;
    int warp = tid >> 5;
    int lane = tid & 31;

    // ---- load weights (split hi/lo) ----
    for (int t = tid; t < 256; t += 128) sw0[t] = w0[t];
    if (tid < 64) { sb0[tid] = b0[tid]; sb1[tid] = b1[tid]; sb2[tid] = b2[tid]; }
    if (tid < 16) sb3[tid] = (tid < 8) ? b3[tid] : 0.0f;
    for (int t = tid; t < 4096; t += 128) {
        int k = t >> 6, n = t & 63;
        __half h, l;
        split_h(w1[t], h, l);
        ((__half*)(sm + SM_B1H))[k*BSTR + n] = h;
        ((__half*)(sm + SM_B1L))[k*BSTR + n] = l;
        split_h(w2[t], h, l);
        ((__half*)(sm + SM_B2H))[k*BSTR + n] = h;
        ((__half*)(sm + SM_B2L))[k*BSTR + n] = l;
    }
    for (int t = tid; t < 1024; t += 128) {
        int k = t >> 4, n = t & 15;
        float v = (n < 8) ? w3[k*8 + n] : 0.0f;
        __half h, l;
        split_h(v, h, l);
        ((__half*)(sm + SM_B3H))[k*16 + n] = h;
        ((__half*)(sm + SM_B3L))[k*16 + n] = l;
    }

    // ---- tile decode ----
    int bid = blockIdx.x;
    int b   = bid / (NTP * 2);
    int rem = bid - b * (NTP * 2);
    int tp  = rem >> 1;
    int jh  = rem & 1;
    int ti = 0;
    while (tp >= NTILE - ti) { tp -= NTILE - ti; ti++; }
    int tj = ti + tp;

    int il = tid >> 3;                  // 0..15
    int jl = tid & 7;                   // 0..7
    int i  = ti * 16 + il;
    int jbase = tj * 16 + jh * 8;
    int j  = jbase + jl;
    int bi = (b << 8) + i;
    int bj = (b << 8) + j;

    // ---- pairwise features ----
    float pxi = g_part[0*BN+bi], pxj = g_part[0*BN+bj];
    float pyi = g_part[1*BN+bi], pyj = g_part[1*BN+bj];
    float pzi = g_part[2*BN+bi], pzj = g_part[2*BN+bj];
    float ei  = g_part[3*BN+bi], ej  = g_part[3*BN+bj];
    float pti = g_part[4*BN+bi], ptj = g_part[4*BN+bj];
    float rpi = g_part[5*BN+bi], rpj = g_part[5*BN+bj];
    float phi_i = g_part[6*BN+bi], phi_j = g_part[6*BN+bj];

    float drap = rpi - rpj;
    float dw = phi_i - phi_j + PI_F;
    dw -= floorf(dw * INV_TWO_PI_F) * TWO_PI_F;
    float dphi = dw - PI_F;
    float delta = sqrtf(drap*drap + dphi*dphi);
    float lndelta = __logf(fmaxf(delta, EPSF));
    float ptmin = fminf(pti, ptj);
    float lnkt = __logf(fmaxf(ptmin * delta, EPSF));
    float lnz  = __logf(fmaxf(__fdividef(ptmin, fmaxf(pti + ptj, EPSF)), EPSF));
    float es = ei + ej, xs = pxi + pxj, ys = pyi + pyj, zs = pzi + pzj;
    float lnm2 = __logf(fmaxf(es*es - xs*xs - ys*ys - zs*zs, EPSF));
    float f0 = lnkt, f1 = lnz, f2 = lndelta, f3 = lnm2;

    __syncthreads();   // weights ready

    // ---- layer 0 (4->64) per-thread fp32 -> gelu -> split fp16 row tid ----
    {
        float act[64];
        #pragma unroll
        for (int c = 0; c < 64; c += 4) {
            float4 a = *(const float4*)&sb0[c];
            float4 w;
            w = *(const float4*)&sw0[0*64 + c];
            a.x = fmaf(f0,w.x,a.x); a.y = fmaf(f0,w.y,a.y); a.z = fmaf(f0,w.z,a.z); a.w = fmaf(f0,w.w,a.w);
            w = *(const float4*)&sw0[1*64 + c];
            a.x = fmaf(f1,w.x,a.x); a.y = fmaf(f1,w.y,a.y); a.z = fmaf(f1,w.z,a.z); a.w = fmaf(f1,w.w,a.w);
            w = *(const float4*)&sw0[2*64 + c];
            a.x = fmaf(f2,w.x,a.x); a.y = fmaf(f2,w.y,a.y); a.z = fmaf(f2,w.z,a.z); a.w = fmaf(f2,w.w,a.w);
            w = *(const float4*)&sw0[3*64 + c];
            a.x = fmaf(f3,w.x,a.x); a.y = fmaf(f3,w.y,a.y); a.z = fmaf(f3,w.z,a.z); a.w = fmaf(f3,w.w,a.w);
            act[c+0] = gelu_t(a.x); act[c+1] = gelu_t(a.y);
            act[c+2] = gelu_t(a.z); act[c+3] = gelu_t(a.w);
        }
        #pragma unroll
        for (int c = 0; c < 64; c += 8) {
            uint4 ph, pl;
            pack8(&act[c], ph, pl);
            *(uint4*)&sAh[tid*ASTR + c] = ph;
            *(uint4*)&sAl[tid*ASTR + c] = pl;
        }
    }
    __syncwarp();

    float* scr = (float*)(sm + SM_SCR) + warp * 320;

    // ---- layers 1 & 2: 64->64 split wmma, gelu, repack in place ----
    #pragma unroll 1
    for (int layer = 0; layer < 2; layer++) {
        const __half* Bh = (const __half*)(sm + (layer == 0 ? SM_B1H : SM_B2H));
        const __half* Bl = (const __half*)(sm + (layer == 0 ? SM_B1L : SM_B2L));
        const float*  bias = (layer == 0) ? sb1 : sb2;
        #pragma unroll
        for (int mt = 0; mt < 2; mt++) {
            int mrow = warp*32 + mt*16;
            wmma::fragment<wmma::matrix_a,16,16,16,__half,wmma::row_major> afh[4], afl[4];
            #pragma unroll
            for (int kt = 0; kt < 4; kt++) {
                wmma::load_matrix_sync(afh[kt], &sAh[mrow*ASTR + kt*16], ASTR);
                wmma::load_matrix_sync(afl[kt], &sAl[mrow*ASTR + kt*16], ASTR);
            }
            #pragma unroll
            for (int nt = 0; nt < 4; nt++) {
                wmma::fragment<wmma::accumulator,16,16,16,float> cf;
                wmma::fill_fragment(cf, 0.0f);
                #pragma unroll
                for (int kt = 0; kt < 4; kt++) {
                    wmma::fragment<wmma::matrix_b,16,16,16,__half,wmma::row_major> bfh, bfl;
                    wmma::load_matrix_sync(bfh, &Bh[kt*16*BSTR + nt*16], BSTR);
                    wmma::load_matrix_sync(bfl, &Bl[kt*16*BSTR + nt*16], BSTR);
                    wmma::mma_sync(cf, afh[kt], bfh, cf);
                    wmma::mma_sync(cf, afh[kt], bfl, cf);
                    wmma::mma_sync(cf, afl[kt], bfh, cf);
                }
                wmma::store_matrix_sync(scr, cf, 20, wmma::mem_row_major);
                __syncwarp();
                {
                    int r  = lane >> 1;
                    int c0 = (lane & 1) * 8;
                    int n  = nt*16 + c0;
                    float g[8];
                    #pragma unroll
                    for (int q = 0; q < 8; q++)
                        g[q] = gelu_t(scr[r*20 + c0 + q] + bias[n + q]);
                    uint4 ph, pl;
                    pack8(g, ph, pl);
                    *(uint4*)&sAh[(mrow + r)*ASTR + n] = ph;
                    *(uint4*)&sAl[(mrow + r)*ASTR + n] = pl;
                }
                __syncwarp();
            }
        }
        __syncwarp();
    }

    // ---- layer 3: 64 -> 8 (padded to 16), split ----
    float outv[8];
    #pragma unroll
    for (int mt = 0; mt < 2; mt++) {
        int mrow = warp*32 + mt*16;
        wmma::fragment<wmma::accumulator,16,16,16,float> cf;
        wmma::fill_fragment(cf, 0.0f);
        #pragma unroll
        for (int kt = 0; kt < 4; kt++) {
            wmma::fragment<wmma::matrix_a,16,16,16,__half,wmma::row_major> afh, afl;
            wmma::fragment<wmma::matrix_b,16,16,16,__half,wmma::row_major> bfh, bfl;
            wmma::load_matrix_sync(afh, &sAh[mrow*ASTR + kt*16], ASTR);
            wmma::load_matrix_sync(afl, &sAl[mrow*ASTR + kt*16], ASTR);
            wmma::load_matrix_sync(bfh, &((__half*)(sm + SM_B3H))[kt*16*16], 16);
            wmma::load_matrix_sync(bfl, &((__half*)(sm + SM_B3L))[kt*16*16], 16);
            wmma::mma_sync(cf, afh, bfh, cf);
            wmma::mma_sync(cf, afh, bfl, cf);
            wmma::mma_sync(cf, afl, bfh, cf);
        }
        wmma::store_matrix_sync(scr, cf, 20, wmma::mem_row_major);
        __syncwarp();
        if ((lane >> 4) == mt) {
            int r = lane & 15;
            #pragma unroll
            for (int h = 0; h < 8; h++) outv[h] = scr[r*20 + h] + sb3[h];
        }
        __syncwarp();
    }

    // ---- direct write [b,h,i,j] ----
    #pragma unroll
    for (int h = 0; h < 8; h++)
        g_bias[(((b*8 + h)*256 + i))*256 + j] = outv[h];

    // ---- mirror write [b,h,j,i] via staging (reuse B1H region) ----
    __syncthreads();
    float* st = (float*)(sm + SM_B1H);     // [8][8][18] floats = 4608B
    #pragma unroll
    for (int h = 0; h < 8; h++) st[(h*8 + jl)*18 + il] = outv[h];
    __syncthreads();
    for (int t = tid; t < 256; t += 128) {
        int h = t >> 5, r = t & 31, jl2 = r >> 2, iq = r & 3;
        const float* s = &st[(h*8 + jl2)*18 + iq*4];
        float4 v = make_float4(s[0], s[1], s[2], s[3]);
        int jrow = jbase + jl2;
        float* q = g_bias + (((b*8 + h)*256 + jrow))*256 + ti*16 + iq*4;
        *(float4*)q = v;
    }
}

// ---------------- kernel 3: QKV projections ----------------
__global__ __launch_bounds__(128) void k_qkv(
    const float* __restrict__ xf,
    const float* __restrict__ wq, const float* __restrict__ wk, const float* __restrict__ wv,
    const float* __restrict__ bq, const float* __restrict__ bk, const float* __restrict__ bv)
{
    __shared__ float xs[16][128];
    int tid = threadIdx.x;
    int r0 = blockIdx.x * 16;
    for (int t = tid; t < 16*128; t += 128) xs[t >> 7][t & 127] = xf[r0*128 + t];
    __syncthreads();

    int d = tid;
    float aq[16], ak[16], av[16];
    float bqv = bq[d], bkv = bk[d], bvv = bv[d];
    #pragma unroll
    for (int r = 0; r < 16; r++) { aq[r] = bqv; ak[r] = bkv; av[r] = bvv; }

    #pragma unroll 4
    for (int k = 0; k < 128; k++) {
        float wqv = wq[k*128 + d];
        float wkv = wk[k*128 + d];
        float wvv = wv[k*128 + d];
        #pragma unroll
        for (int r = 0; r < 16; r++) {
            float x = xs[r][k];
            aq[r] = fmaf(x, wqv, aq[r]);
            ak[r] = fmaf(x, wkv, ak[r]);
            av[r] = fmaf(x, wvv, av[r]);
        }
    }
    #pragma unroll
    for (int r = 0; r < 16; r++) {
        int row = r0 + r;
        g_q[row*128 + d] = aq[r];
        g_k[row*128 + d] = ak[r];
        g_v[row*128 + d] = av[r];
    }
}

// ---------------- kernel 4: attention ----------------
__global__ __launch_bounds__(256) void k_attn() {
    int bid = blockIdx.x;
    int it = bid & 31;
    int h  = (bid >> 5) & 7;
    int b  = bid >> 8;

    __shared__ float ks[256][20];
    __shared__ float vs[256][20];
    __shared__ float ps[8][256];

    int tid = threadIdx.x;
    {
        int j = tid;
        const float* kp = g_k + (b*256 + j)*128 + h*16;
        const float* vp = g_v + (b*256 + j)*128 + h*16;
        #pragma unroll
        for (int d = 0; d < 16; d += 4) {
            *(float4*)&ks[j][d] = *(const float4*)&kp[d];
            *(float4*)&vs[j][d] = *(const float4*)&vp[d];
        }
    }
    __syncthreads();

    int w = tid >> 5;
    int lane = tid & 31;
    int i = it * 8 + w;

    float q[16];
    const float* qp = g_q + (b*256 + i)*128 + h*16;
    #pragma unroll
    for (int d = 0; d < 16; d++) q[d] = qp[d];

    const float* bp = g_bias + ((b*8 + h)*256 + i)*256;

    float s[8];
    float m = -1e30f;
    #pragma unroll
    for (int jj = 0; jj < 8; jj++) {
        int j = jj*32 + lane;
        float4 k0 = *(const float4*)&ks[j][0];
        float4 k1 = *(const float4*)&ks[j][4];
        float4 k2 = *(const float4*)&ks[j][8];
        float4 k3 = *(const float4*)&ks[j][12];
        float acc = q[0]*k0.x;
        acc = fmaf(q[1],k0.y,acc);  acc = fmaf(q[2],k0.z,acc);  acc = fmaf(q[3],k0.w,acc);
        acc = fmaf(q[4],k1.x,acc);  acc = fmaf(q[5],k1.y,acc);  acc = fmaf(q[6],k1.z,acc);  acc = fmaf(q[7],k1.w,acc);
        acc = fmaf(q[8],k2.x,acc);  acc = fmaf(q[9],k2.y,acc);  acc = fmaf(q[10],k2.z,acc); acc = fmaf(q[11],k2.w,acc);
        acc = fmaf(q[12],k3.x,acc); acc = fmaf(q[13],k3.y,acc); acc = fmaf(q[14],k3.z,acc); acc = fmaf(q[15],k3.w,acc);
        s[jj] = acc * 0.25f + bp[j];
        m = fmaxf(m, s[jj]);
    }
    #pragma unroll
    for (int off = 16; off >= 1; off >>= 1) m = fmaxf(m, __shfl_xor_sync(0xffffffffu, m, off));

    float sum = 0.0f;
    #pragma unroll
    for (int jj = 0; jj < 8; jj++) { s[jj] = __expf(s[jj] - m); sum += s[jj]; }
    #pragma unroll
    for (int off = 16; off >= 1; off >>= 1) sum += __shfl_xor_sync(0xffffffffu, sum, off);
    float inv = __fdividef(1.0f, sum);

    #pragma unroll
    for (int jj = 0; jj < 8; jj++) ps[w][jj*32 + lane] = s[jj] * inv;
    __syncwarp();

    // PV: lane = (jp | d4): 8-way j split, float4 over d, shuffle combine
    {
        int d4 = lane & 3;
        int jp = lane >> 2;
        float4 acc = make_float4(0.f, 0.f, 0.f, 0.f);
        #pragma unroll 4
        for (int jj = 0; jj < 32; jj++) {
            int j = jj*8 + jp;
            float p = ps[w][j];
            float4 v = *(const float4*)&vs[j][d4*4];
            acc.x = fmaf(p, v.x, acc.x);
            acc.y = fmaf(p, v.y, acc.y);
            acc.z = fmaf(p, v.z, acc.z);
            acc.w = fmaf(p, v.w, acc.w);
        }
        #pragma unroll
        for (int off = 4; off <= 16; off <<= 1) {
            acc.x += __shfl_xor_sync(0xffffffffu, acc.x, off);
            acc.y += __shfl_xor_sync(0xffffffffu, acc.y, off);
            acc.z += __shfl_xor_sync(0xffffffffu, acc.z, off);
            acc.w += __shfl_xor_sync(0xffffffffu, acc.w, off);
        }
        if (jp == 0)
            *(float4*)&g_ao[(b*256 + i)*128 + h*16 + d4*4] = acc;
    }
}

// ---------------- kernel 5: output projection ----------------
__global__ __launch_bounds__(128) void k_outproj(
    const float* __restrict__ wo, const float* __restrict__ bo, float* __restrict__ out)
{
    __shared__ float xs[16][128];
    int tid = threadIdx.x;
    int r0 = blockIdx.x * 16;
    for (int t = tid; t < 16*128; t += 128) xs[t >> 7][t & 127] = g_ao[r0*128 + t];
    __syncthreads();

    int d = tid;
    float acc[16];
    float bv = bo[d];
    #pragma unroll
    for (int r = 0; r < 16; r++) acc[r] = bv;

    #pragma unroll 4
    for (int k = 0; k < 128; k++) {
        float wv = wo[k*128 + d];
        #pragma unroll
        for (int r = 0; r < 16; r++) acc[r] = fmaf(xs[r][k], wv, acc[r]);
    }
    #pragma unroll
    for (int r = 0; r < 16; r++) out[(r0 + r)*128 + d] = acc[r];
}

// ---------------- launch ----------------
extern "C" void kernel_launch(void* const* d_in, const int* in_sizes, int n_in,
                              void* d_out, int out_size) {
    (void)in_sizes; (void)n_in; (void)out_size;
    const float* x_pf   = (const float*)d_in[0];
    const float* x_feat = (const float*)d_in[1];
    const float* w0 = (const float*)d_in[2];
    const float* b0 = (const float*)d_in[3];
    const float* w1 = (const float*)d_in[4];
    const float* b1 = (const float*)d_in[5];
    const float* w2 = (const float*)d_in[6];
    const float* b2 = (const float*)d_in[7];
    const float* w3 = (const float*)d_in[8];
    const float* b3 = (const float*)d_in[9];
    const float* wq = (const float*)d_in[10];
    const float* wk = (const float*)d_in[11];
    const float* wv = (const float*)d_in[12];
    const float* wo = (const float*)d_in[13];
    const float* bq = (const float*)d_in[14];
    const float* bk = (const float*)d_in[15];
    const float* bv = (const float*)d_in[16];
    const float* bo = (const float*)d_in[17];

    cudaFuncSetAttribute(k_pair, cudaFuncAttributeMaxDynamicSharedMemorySize, SM_TOT);

    k_part<<<16, 256>>>(x_pf);
    k_pair<<<BB*NTP*2, 128, SM_TOT>>>(w0, b0, w1, b1, w2, b2, w3, b3);
    k_qkv<<<256, 128>>>(x_feat, wq, wk, wv, bq, bk, bv);
    k_attn<<<4096, 256>>>();
    k_outproj<<<256, 128>>>(wo, bo, (float*)d_out);
}

// round 12
// speedup vs baseline: 5.4485x; 1.2933x over previous
#include <cuda_runtime.h>
#include <cuda_fp16.h>
#include <mma.h>
#include <math.h>
#include <stdint.h>

using namespace nvcuda;

#define BB 16
#define NN 256
#define DD 128
#define HH 8
#define HDIM 16
#define BN (BB*NN)          // 4096
#define EPSF 1e-8f
#define PI_F 3.14159265358979323846f
#define TWO_PI_F 6.28318530717958647692f
#define INV_TWO_PI_F 0.15915494309189533577f
#define NTILE 16
#define NTP 136             // upper-triangle tile pairs 16*17/2

#define ASTR 72             // A row stride in halves (144B)
#define BSTR 72             // B row stride in halves

// ---- k_pair dynamic SMEM layout (bytes) ----
#define SM_AH   0                      // 128*72*2 = 18432
#define SM_AL   18432                  // 18432
#define SM_B1H  36864                  // 9216
#define SM_B1L  46080                  // 9216
#define SM_B2H  55296                  // 9216
#define SM_B2L  64512                  // 9216
#define SM_B3H  73728                  // 2048
#define SM_B3L  75776                  // 2048
#define SM_SCR  77824                  // 4*16*20*4 = 5120
#define SM_W0   82944                  // 1024
#define SM_SB0  83968                  // 256
#define SM_SB1  84224                  // 256
#define SM_SB2  84480                  // 256
#define SM_SB3  84736                  // 64
#define SM_TOT  84800

// ---- k_attn dynamic SMEM layout ----
#define AT_KS   0                      // 256*20*4 = 20480
#define AT_VS   20480                  // 20480
#define AT_PS   40960                  // 16*256*4 = 16384
#define AT_TOT  57344

// ---------------- scratch ----------------
__device__ float g_part[7*BN];
__device__ float g_bias[BB*HH*NN*NN];
__device__ float g_q[BN*DD];
__device__ float g_k[BN*DD];
__device__ float g_v[BN*DD];
__device__ float g_ao[BN*DD];
// pre-split fp16 weights (zero-init; pads stay 0)
__device__ __align__(16) __half g_w1h[64*BSTR];
__device__ __align__(16) __half g_w1l[64*BSTR];
__device__ __align__(16) __half g_w2h[64*BSTR];
__device__ __align__(16) __half g_w2l[64*BSTR];
__device__ __align__(16) __half g_w3h[64*16];
__device__ __align__(16) __half g_w3l[64*16];

// ---------------- helpers ----------------
__device__ __forceinline__ void split_h(float a, __half& hi, __half& lo) {
    hi = __float2half_rn(a);
    lo = __float2half_rn(a - __half2float(hi));
}

// fast tanh-based GELU via MUFU.TANH
__device__ __forceinline__ float gelu_t(float x) {
    const float c = 0.7978845608028654f;   // sqrt(2/pi)
    float u = c * fmaf(0.044715f * x, x * x, x);
    float t;
    asm("tanh.approx.f32 %0, %1;" : "=f"(t) : "f"(u));
    return 0.5f * x * (1.0f + t);
}

// pack 8 floats into hi uint4 + lo uint4
__device__ __forceinline__ void pack8(const float* v, uint4& ph, uint4& pl) {
    uint32_t* phu = (uint32_t*)&ph;
    uint32_t* plu = (uint32_t*)&pl;
    #pragma unroll
    for (int q = 0; q < 4; q++) {
        __half2 hh = __floats2half2_rn(v[2*q+0], v[2*q+1]);
        float2 hf = __half22float2(hh);
        __half2 ll = __floats2half2_rn(v[2*q+0] - hf.x, v[2*q+1] - hf.y);
        phu[q] = *(uint32_t*)&hh;
        plu[q] = *(uint32_t*)&ll;
    }
}

// ---------------- kernel 0: pre-split the MLP weights ----------------
__global__ void k_wsplit(const float* __restrict__ w1, const float* __restrict__ w2,
                         const float* __restrict__ w3) {
    int t = blockIdx.x * 256 + threadIdx.x;
    if (t < 4096) {
        int k = t >> 6, n = t & 63;
        __half h, l;
        split_h(w1[t], h, l);
        g_w1h[k*BSTR + n] = h; g_w1l[k*BSTR + n] = l;
        split_h(w2[t], h, l);
        g_w2h[k*BSTR + n] = h; g_w2l[k*BSTR + n] = l;
    }
    if (t < 1024) {
        int k = t >> 4, n = t & 15;
        float v = (n < 8) ? w3[k*8 + n] : 0.0f;
        __half h, l;
        split_h(v, h, l);
        g_w3h[k*16 + n] = h; g_w3l[k*16 + n] = l;
    }
}

// ---------------- kernel 1: per-particle features ----------------
__global__ void k_part(const float* __restrict__ x_pf) {
    int idx = blockIdx.x * blockDim.x + threadIdx.x;
    if (idx >= BN) return;
    int b = idx >> 8;
    int n = idx & 255;
    const float* base = x_pf + b * 4 * NN + n;
    float px = base[0];
    float py = base[NN];
    float pz = base[2*NN];
    float e  = base[3*NN];
    float pt  = sqrtf(fmaxf(px*px + py*py, EPSF));
    float rap = 0.5f * log1pf(2.0f * pz / fmaxf(e - pz, 1e-20f));
    float phi = atan2f(py, px);
    g_part[0*BN + idx] = px;
    g_part[1*BN + idx] = py;
    g_part[2*BN + idx] = pz;
    g_part[3*BN + idx] = e;
    g_part[4*BN + idx] = pt;
    g_part[5*BN + idx] = rap;
    g_part[6*BN + idx] = phi;
}

// ---------------- kernel 2: pair MLP via split fp16 wmma ----------------
__global__ __launch_bounds__(128) void k_pair(
    const float* __restrict__ w0, const float* __restrict__ b0,
    const float* __restrict__ b1, const float* __restrict__ b2,
    const float* __restrict__ b3)
{
    extern __shared__ __align__(16) unsigned char sm[];
    __half* sAh = (__half*)(sm + SM_AH);
    __half* sAl = (__half*)(sm + SM_AL);
    float* sw0 = (float*)(sm + SM_W0);
    float* sb0 = (float*)(sm + SM_SB0);
    float* sb1 = (float*)(sm + SM_SB1);
    float* sb2 = (float*)(sm + SM_SB2);
    float* sb3 = (float*)(sm + SM_SB3);

    int tid = threadIdx.x;
    int warp = tid >> 5;
    int lane = tid & 31;

    // ---- copy pre-split weights (vector copies) ----
    {
        const uint4* s1h = (const uint4*)g_w1h;
        const uint4* s1l = (const uint4*)g_w1l;
        const uint4* s2h = (const uint4*)g_w2h;
        const uint4* s2l = (const uint4*)g_w2l;
        uint4* d1h = (uint4*)(sm + SM_B1H);
        uint4* d1l = (uint4*)(sm + SM_B1L);
        uint4* d2h = (uint4*)(sm + SM_B2H);
        uint4* d2l = (uint4*)(sm + SM_B2L);
        for (int t = tid; t < 576; t += 128) {
            d1h[t] = s1h[t]; d1l[t] = s1l[t];
            d2h[t] = s2h[t]; d2l[t] = s2l[t];
        }
        const uint4* s3h = (const uint4*)g_w3h;
        const uint4* s3l = (const uint4*)g_w3l;
        uint4* d3h = (uint4*)(sm + SM_B3H);
        uint4* d3l = (uint4*)(sm + SM_B3L);
        if (tid < 128) { d3h[tid] = s3h[tid]; d3l[tid] = s3l[tid]; }
    }
    for (int t = tid; t < 256; t += 128) sw0[t] = w0[t];
    if (tid < 64) { sb0[tid] = b0[tid]; sb1[tid] = b1[tid]; sb2[tid] = b2[tid]; }
    if (tid < 16) sb3[tid] = (tid < 8) ? b3[tid] : 0.0f;

    // ---- tile decode ----
    int bid = blockIdx.x;
    int b   = bid / (NTP * 2);
    int rem = bid - b * (NTP * 2);
    int tp  = rem >> 1;
    int jh  = rem & 1;
    int ti = 0;
    while (tp >= NTILE - ti) { tp -= NTILE - ti; ti++; }
    int tj = ti + tp;

    int il = tid >> 3;                  // 0..15
    int jl = tid & 7;                   // 0..7
    int i  = ti * 16 + il;
    int jbase = tj * 16 + jh * 8;
    int j  = jbase + jl;
    int bi = (b << 8) + i;
    int bj = (b << 8) + j;

    // ---- pairwise features ----
    float pxi = g_part[0*BN+bi], pxj = g_part[0*BN+bj];
    float pyi = g_part[1*BN+bi], pyj = g_part[1*BN+bj];
    float pzi = g_part[2*BN+bi], pzj = g_part[2*BN+bj];
    float ei  = g_part[3*BN+bi], ej  = g_part[3*BN+bj];
    float pti = g_part[4*BN+bi], ptj = g_part[4*BN+bj];
    float rpi = g_part[5*BN+bi], rpj = g_part[5*BN+bj];
    float phi_i = g_part[6*BN+bi], phi_j = g_part[6*BN+bj];

    float drap = rpi - rpj;
    float dw = phi_i - phi_j + PI_F;
    dw -= floorf(dw * INV_TWO_PI_F) * TWO_PI_F;
    float dphi = dw - PI_F;
    float delta = sqrtf(drap*drap + dphi*dphi);
    float lndelta = __logf(fmaxf(delta, EPSF));
    float ptmin = fminf(pti, ptj);
    float lnkt = __logf(fmaxf(ptmin * delta, EPSF));
    float lnz  = __logf(fmaxf(__fdividef(ptmin, fmaxf(pti + ptj, EPSF)), EPSF));
    float es = ei + ej, xs = pxi + pxj, ys = pyi + pyj, zs = pzi + pzj;
    float lnm2 = __logf(fmaxf(es*es - xs*xs - ys*ys - zs*zs, EPSF));
    float f0 = lnkt, f1 = lnz, f2 = lndelta, f3 = lnm2;

    __syncthreads();   // weights ready

    // ---- layer 0 (4->64) per-thread fp32 -> gelu -> split fp16 row tid ----
    {
        float act[64];
        #pragma unroll
        for (int c = 0; c < 64; c += 4) {
            float4 a = *(const float4*)&sb0[c];
            float4 w;
            w = *(const float4*)&sw0[0*64 + c];
            a.x = fmaf(f0,w.x,a.x); a.y = fmaf(f0,w.y,a.y); a.z = fmaf(f0,w.z,a.z); a.w = fmaf(f0,w.w,a.w);
            w = *(const float4*)&sw0[1*64 + c];
            a.x = fmaf(f1,w.x,a.x); a.y = fmaf(f1,w.y,a.y); a.z = fmaf(f1,w.z,a.z); a.w = fmaf(f1,w.w,a.w);
            w = *(const float4*)&sw0[2*64 + c];
            a.x = fmaf(f2,w.x,a.x); a.y = fmaf(f2,w.y,a.y); a.z = fmaf(f2,w.z,a.z); a.w = fmaf(f2,w.w,a.w);
            w = *(const float4*)&sw0[3*64 + c];
            a.x = fmaf(f3,w.x,a.x); a.y = fmaf(f3,w.y,a.y); a.z = fmaf(f3,w.z,a.z); a.w = fmaf(f3,w.w,a.w);
            act[c+0] = gelu_t(a.x); act[c+1] = gelu_t(a.y);
            act[c+2] = gelu_t(a.z); act[c+3] = gelu_t(a.w);
        }
        #pragma unroll
        for (int c = 0; c < 64; c += 8) {
            uint4 ph, pl;
            pack8(&act[c], ph, pl);
            *(uint4*)&sAh[tid*ASTR + c] = ph;
            *(uint4*)&sAl[tid*ASTR + c] = pl;
        }
    }
    __syncwarp();

    float* scr = (float*)(sm + SM_SCR) + warp * 320;

    // ---- layers 1 & 2: 64->64 split wmma, gelu, repack in place ----
    #pragma unroll 1
    for (int layer = 0; layer < 2; layer++) {
        const __half* Bh = (const __half*)(sm + (layer == 0 ? SM_B1H : SM_B2H));
        const __half* Bl = (const __half*)(sm + (layer == 0 ? SM_B1L : SM_B2L));
        const float*  bias = (layer == 0) ? sb1 : sb2;
        #pragma unroll
        for (int mt = 0; mt < 2; mt++) {
            int mrow = warp*32 + mt*16;
            wmma::fragment<wmma::matrix_a,16,16,16,__half,wmma::row_major> afh[4], afl[4];
            #pragma unroll
            for (int kt = 0; kt < 4; kt++) {
                wmma::load_matrix_sync(afh[kt], &sAh[mrow*ASTR + kt*16], ASTR);
                wmma::load_matrix_sync(afl[kt], &sAl[mrow*ASTR + kt*16], ASTR);
            }
            #pragma unroll
            for (int nt = 0; nt < 4; nt++) {
                wmma::fragment<wmma::accumulator,16,16,16,float> cf;
                wmma::fill_fragment(cf, 0.0f);
                #pragma unroll
                for (int kt = 0; kt < 4; kt++) {
                    wmma::fragment<wmma::matrix_b,16,16,16,__half,wmma::row_major> bfh, bfl;
                    wmma::load_matrix_sync(bfh, &Bh[kt*16*BSTR + nt*16], BSTR);
                    wmma::load_matrix_sync(bfl, &Bl[kt*16*BSTR + nt*16], BSTR);
                    wmma::mma_sync(cf, afh[kt], bfh, cf);
                    wmma::mma_sync(cf, afh[kt], bfl, cf);
                    wmma::mma_sync(cf, afl[kt], bfh, cf);
                }
                wmma::store_matrix_sync(scr, cf, 20, wmma::mem_row_major);
                __syncwarp();
                {
                    int r  = lane >> 1;
                    int c0 = (lane & 1) * 8;
                    int n  = nt*16 + c0;
                    float g[8];
                    #pragma unroll
                    for (int q = 0; q < 8; q++)
                        g[q] = gelu_t(scr[r*20 + c0 + q] + bias[n + q]);
                    uint4 ph, pl;
                    pack8(g, ph, pl);
                    *(uint4*)&sAh[(mrow + r)*ASTR + n] = ph;
                    *(uint4*)&sAl[(mrow + r)*ASTR + n] = pl;
                }
                __syncwarp();
            }
        }
        __syncwarp();
    }

    // ---- layer 3: 64 -> 8 (padded to 16), split ----
    float outv[8];
    #pragma unroll
    for (int mt = 0; mt < 2; mt++) {
        int mrow = warp*32 + mt*16;
        wmma::fragment<wmma::accumulator,16,16,16,float> cf;
        wmma::fill_fragment(cf, 0.0f);
        #pragma unroll
        for (int kt = 0; kt < 4; kt++) {
            wmma::fragment<wmma::matrix_a,16,16,16,__half,wmma::row_major> afh, afl;
            wmma::fragment<wmma::matrix_b,16,16,16,__half,wmma::row_major> bfh, bfl;
            wmma::load_matrix_sync(afh, &sAh[mrow*ASTR + kt*16], ASTR);
            wmma::load_matrix_sync(afl, &sAl[mrow*ASTR + kt*16], ASTR);
            wmma::load_matrix_sync(bfh, &((__half*)(sm + SM_B3H))[kt*16*16], 16);
            wmma::load_matrix_sync(bfl, &((__half*)(sm + SM_B3L))[kt*16*16], 16);
            wmma::mma_sync(cf, afh, bfh, cf);
            wmma::mma_sync(cf, afh, bfl, cf);
            wmma::mma_sync(cf, afl, bfh, cf);
        }
        wmma::store_matrix_sync(scr, cf, 20, wmma::mem_row_major);
        __syncwarp();
        if ((lane >> 4) == mt) {
            int r = lane & 15;
            #pragma unroll
            for (int h = 0; h < 8; h++) outv[h] = scr[r*20 + h] + sb3[h];
        }
        __syncwarp();
    }

    // ---- direct write [b,h,i,j] ----
    #pragma unroll
    for (int h = 0; h < 8; h++)
        g_bias[(((b*8 + h)*256 + i))*256 + j] = outv[h];

    // ---- mirror write [b,h,j,i] via staging (reuse B1H region) ----
    __syncthreads();
    float* st = (float*)(sm + SM_B1H);     // [8][8][18] floats = 4608B
    #pragma unroll
    for (int h = 0; h < 8; h++) st[(h*8 + jl)*18 + il] = outv[h];
    __syncthreads();
    for (int t = tid; t < 256; t += 128) {
        int h = t >> 5, r = t & 31, jl2 = r >> 2, iq = r & 3;
        const float* s = &st[(h*8 + jl2)*18 + iq*4];
        float4 v = make_float4(s[0], s[1], s[2], s[3]);
        int jrow = jbase + jl2;
        float* q = g_bias + (((b*8 + h)*256 + jrow))*256 + ti*16 + iq*4;
        *(float4*)q = v;
    }
}

// ---------------- kernel 3: QKV projections ----------------
__global__ __launch_bounds__(128) void k_qkv(
    const float* __restrict__ xf,
    const float* __restrict__ wq, const float* __restrict__ wk, const float* __restrict__ wv,
    const float* __restrict__ bq, const float* __restrict__ bk, const float* __restrict__ bv)
{
    __shared__ float xs[16][128];
    int tid = threadIdx.x;
    int r0 = blockIdx.x * 16;
    for (int t = tid; t < 16*128; t += 128) xs[t >> 7][t & 127] = xf[r0*128 + t];
    __syncthreads();

    int d = tid;
    float aq[16], ak[16], av[16];
    float bqv = bq[d], bkv = bk[d], bvv = bv[d];
    #pragma unroll
    for (int r = 0; r < 16; r++) { aq[r] = bqv; ak[r] = bkv; av[r] = bvv; }

    #pragma unroll 4
    for (int k = 0; k < 128; k++) {
        float wqv = wq[k*128 + d];
        float wkv = wk[k*128 + d];
        float wvv = wv[k*128 + d];
        #pragma unroll
        for (int r = 0; r < 16; r++) {
            float x = xs[r][k];
            aq[r] = fmaf(x, wqv, aq[r]);
            ak[r] = fmaf(x, wkv, ak[r]);
            av[r] = fmaf(x, wvv, av[r]);
        }
    }
    #pragma unroll
    for (int r = 0; r < 16; r++) {
        int row = r0 + r;
        g_q[row*128 + d] = aq[r];
        g_k[row*128 + d] = ak[r];
        g_v[row*128 + d] = av[r];
    }
}

// ---------------- kernel 4: attention, 2 rows per warp, 32 rows per block ----------------
__global__ __launch_bounds__(256, 2) void k_attn() {
    extern __shared__ __align__(16) unsigned char smd[];
    float (*ks)[20] = (float(*)[20])(smd + AT_KS);
    float (*vs)[20] = (float(*)[20])(smd + AT_VS);
    float (*ps)[256] = (float(*)[256])(smd + AT_PS);

    int bid = blockIdx.x;          // grid = 16*8*8 = 1024
    int it = bid & 7;              // 32-row tile
    int h  = (bid >> 3) & 7;
    int b  = bid >> 6;

    int tid = threadIdx.x;
    {
        int j = tid;
        const float* kp = g_k + (b*256 + j)*128 + h*16;
        const float* vp = g_v + (b*256 + j)*128 + h*16;
        #pragma unroll
        for (int d = 0; d < 16; d += 4) {
            *(float4*)&ks[j][d] = *(const float4*)&kp[d];
            *(float4*)&vs[j][d] = *(const float4*)&vp[d];
        }
    }
    __syncthreads();

    int w = tid >> 5;
    int lane = tid & 31;

    #pragma unroll 1
    for (int pr = 0; pr < 2; pr++) {
        int i0 = it*32 + w*4 + pr*2;           // rows i0, i0+1

        const float* qp0 = g_q + (b*256 + i0)*128 + h*16;
        float q0[16], q1[16];
        #pragma unroll
        for (int d = 0; d < 16; d++) { q0[d] = qp0[d]; q1[d] = qp0[128 + d]; }

        const float* bp0 = g_bias + ((b*8 + h)*256 + i0)*256;
        float bb0[8], bb1[8];
        #pragma unroll
        for (int jj = 0; jj < 8; jj++) {
            bb0[jj] = bp0[jj*32 + lane];
            bb1[jj] = bp0[256 + jj*32 + lane];
        }

        float s0[8], s1[8];
        float m0 = -1e30f, m1 = -1e30f;
        #pragma unroll
        for (int jj = 0; jj < 8; jj++) {
            int j = jj*32 + lane;
            float4 k0 = *(const float4*)&ks[j][0];
            float4 k1 = *(const float4*)&ks[j][4];
            float4 k2 = *(const float4*)&ks[j][8];
            float4 k3 = *(const float4*)&ks[j][12];
            // row 0: two parallel 8-chains
            float e0 = q0[0]*k0.x;
            e0 = fmaf(q0[1],k0.y,e0); e0 = fmaf(q0[2],k0.z,e0); e0 = fmaf(q0[3],k0.w,e0);
            e0 = fmaf(q0[4],k1.x,e0); e0 = fmaf(q0[5],k1.y,e0); e0 = fmaf(q0[6],k1.z,e0); e0 = fmaf(q0[7],k1.w,e0);
            float e1 = q0[8]*k2.x;
            e1 = fmaf(q0[9],k2.y,e1);  e1 = fmaf(q0[10],k2.z,e1); e1 = fmaf(q0[11],k2.w,e1);
            e1 = fmaf(q0[12],k3.x,e1); e1 = fmaf(q0[13],k3.y,e1); e1 = fmaf(q0[14],k3.z,e1); e1 = fmaf(q0[15],k3.w,e1);
            s0[jj] = (e0 + e1) * 0.25f + bb0[jj];
            m0 = fmaxf(m0, s0[jj]);
            // row 1
            float f0 = q1[0]*k0.x;
            f0 = fmaf(q1[1],k0.y,f0); f0 = fmaf(q1[2],k0.z,f0); f0 = fmaf(q1[3],k0.w,f0);
            f0 = fmaf(q1[4],k1.x,f0); f0 = fmaf(q1[5],k1.y,f0); f0 = fmaf(q1[6],k1.z,f0); f0 = fmaf(q1[7],k1.w,f0);
            float f1 = q1[8]*k2.x;
            f1 = fmaf(q1[9],k2.y,f1);  f1 = fmaf(q1[10],k2.z,f1); f1 = fmaf(q1[11],k2.w,f1);
            f1 = fmaf(q1[12],k3.x,f1); f1 = fmaf(q1[13],k3.y,f1); f1 = fmaf(q1[14],k3.z,f1); f1 = fmaf(q1[15],k3.w,f1);
            s1[jj] = (f0 + f1) * 0.25f + bb1[jj];
            m1 = fmaxf(m1, s1[jj]);
        }
        #pragma unroll
        for (int off = 16; off >= 1; off >>= 1) {
            m0 = fmaxf(m0, __shfl_xor_sync(0xffffffffu, m0, off));
            m1 = fmaxf(m1, __shfl_xor_sync(0xffffffffu, m1, off));
        }
        float sum0 = 0.0f, sum1 = 0.0f;
        #pragma unroll
        for (int jj = 0; jj < 8; jj++) {
            s0[jj] = __expf(s0[jj] - m0); sum0 += s0[jj];
            s1[jj] = __expf(s1[jj] - m1); sum1 += s1[jj];
        }
        #pragma unroll
        for (int off = 16; off >= 1; off >>= 1) {
            sum0 += __shfl_xor_sync(0xffffffffu, sum0, off);
            sum1 += __shfl_xor_sync(0xffffffffu, sum1, off);
        }
        float inv0 = __fdividef(1.0f, sum0);
        float inv1 = __fdividef(1.0f, sum1);

        int sl0 = w*2, sl1 = w*2 + 1;
        #pragma unroll
        for (int jj = 0; jj < 8; jj++) {
            ps[sl0][jj*32 + lane] = s0[jj] * inv0;
            ps[sl1][jj*32 + lane] = s1[jj] * inv1;
        }
        __syncwarp();

        // PV: lane = (jp | d4): 8-way j split, float4 over d; V shared by both rows
        {
            int d4 = lane & 3;
            int jp = lane >> 2;
            float4 a0 = make_float4(0.f,0.f,0.f,0.f);
            float4 a1 = make_float4(0.f,0.f,0.f,0.f);
            #pragma unroll 4
            for (int jj = 0; jj < 32; jj++) {
                int j = jj*8 + jp;
                float4 v = *(const float4*)&vs[j][d4*4];
                float p0 = ps[sl0][j];
                float p1 = ps[sl1][j];
                a0.x = fmaf(p0, v.x, a0.x); a0.y = fmaf(p0, v.y, a0.y);
                a0.z = fmaf(p0, v.z, a0.z); a0.w = fmaf(p0, v.w, a0.w);
                a1.x = fmaf(p1, v.x, a1.x); a1.y = fmaf(p1, v.y, a1.y);
                a1.z = fmaf(p1, v.z, a1.z); a1.w = fmaf(p1, v.w, a1.w);
            }
            #pragma unroll
            for (int off = 4; off <= 16; off <<= 1) {
                a0.x += __shfl_xor_sync(0xffffffffu, a0.x, off);
                a0.y += __shfl_xor_sync(0xffffffffu, a0.y, off);
                a0.z += __shfl_xor_sync(0xffffffffu, a0.z, off);
                a0.w += __shfl_xor_sync(0xffffffffu, a0.w, off);
                a1.x += __shfl_xor_sync(0xffffffffu, a1.x, off);
                a1.y += __shfl_xor_sync(0xffffffffu, a1.y, off);
                a1.z += __shfl_xor_sync(0xffffffffu, a1.z, off);
                a1.w += __shfl_xor_sync(0xffffffffu, a1.w, off);
            }
            if (jp == 0) {
                *(float4*)&g_ao[(b*256 + i0)*128 + h*16 + d4*4] = a0;
                *(float4*)&g_ao[(b*256 + i0 + 1)*128 + h*16 + d4*4] = a1;
            }
        }
        __syncwarp();
    }
}

// ---------------- kernel 5: output projection ----------------
__global__ __launch_bounds__(128) void k_outproj(
    const float* __restrict__ wo, const float* __restrict__ bo, float* __restrict__ out)
{
    __shared__ float xs[16][128];
    int tid = threadIdx.x;
    int r0 = blockIdx.x * 16;
    for (int t = tid; t < 16*128; t += 128) xs[t >> 7][t & 127] = g_ao[r0*128 + t];
    __syncthreads();

    int d = tid;
    float acc[16];
    float bv = bo[d];
    #pragma unroll
    for (int r = 0; r < 16; r++) acc[r] = bv;

    #pragma unroll 4
    for (int k = 0; k < 128; k++) {
        float wv = wo[k*128 + d];
        #pragma unroll
        for (int r = 0; r < 16; r++) acc[r] = fmaf(xs[r][k], wv, acc[r]);
    }
    #pragma unroll
    for (int r = 0; r < 16; r++) out[(r0 + r)*128 + d] = acc[r];
}

// ---------------- launch ----------------
extern "C" void kernel_launch(void* const* d_in, const int* in_sizes, int n_in,
                              void* d_out, int out_size) {
    (void)in_sizes; (void)n_in; (void)out_size;
    const float* x_pf   = (const float*)d_in[0];
    const float* x_feat = (const float*)d_in[1];
    const float* w0 = (const float*)d_in[2];
    const float* b0 = (const float*)d_in[3];
    const float* w1 = (const float*)d_in[4];
    const float* b1 = (const float*)d_in[5];
    const float* w2 = (const float*)d_in[6];
    const float* b2 = (const float*)d_in[7];
    const float* w3 = (const float*)d_in[8];
    const float* b3 = (const float*)d_in[9];
    const float* wq = (const float*)d_in[10];
    const float* wk = (const float*)d_in[11];
    const float* wv = (const float*)d_in[12];
    const float* wo = (const float*)d_in[13];
    const float* bq = (const float*)d_in[14];
    const float* bk = (const float*)d_in[15];
    const float* bv = (const float*)d_in[16];
    const float* bo = (const float*)d_in[17];

    cudaFuncSetAttribute(k_pair, cudaFuncAttributeMaxDynamicSharedMemorySize, SM_TOT);
    cudaFuncSetAttribute(k_attn, cudaFuncAttributeMaxDynamicSharedMemorySize, AT_TOT);

    k_wsplit<<<16, 256>>>(w1, w2, w3);
    k_part<<<16, 256>>>(x_pf);
    k_pair<<<BB*NTP*2, 128, SM_TOT>>>(w0, b0, b1, b2, b3);
    k_qkv<<<256, 128>>>(x_feat, wq, wk, wv, bq, bk, bv);
    k_attn<<<1024, 256, AT_TOT>>>();
    k_outproj<<<256, 128>>>(wo, bo, (float*)d_out);
}

// round 13
// speedup vs baseline: 6.3544x; 1.1663x over previous
#include <cuda_runtime.h>
#include <cuda_fp16.h>
#include <math.h>
#include <stdint.h>

#define BB 16
#define NN 256
#define DD 128
#define HH 8
#define HDIM 16
#define BN (BB*NN)          // 4096
#define EPSF 1e-8f
#define PI_F 3.14159265358979323846f
#define TWO_PI_F 6.28318530717958647692f
#define INV_TWO_PI_F 0.15915494309189533577f
#define NTILE 16
#define NTP 136             // upper-triangle tile pairs 16*17/2

#define ASTR 72             // layer0 activation row stride (halves)
#define BSTR 72             // B1/B2 row stride (halves)
#define B3STR 24            // B3 row stride (halves)

// ---- k_pair dynamic SMEM layout (bytes) ----
#define SM_AH   0                      // 128*72*2 = 18432
#define SM_AL   18432                  // 18432
#define SM_B1H  36864                  // 64*72*2 = 9216
#define SM_B1L  46080                  // 9216
#define SM_B2H  55296                  // 9216
#define SM_B2L  64512                  // 9216
#define SM_B3H  73728                  // 64*24*2 = 3072
#define SM_B3L  76800                  // 3072
#define SM_SCR  79872                  // 4 warps * 288 floats * 4 = 4608
#define SM_W0   84480                  // 1024
#define SM_SB0  85504                  // 256
#define SM_SB1  85760                  // 256
#define SM_SB2  86016                  // 256
#define SM_SB3  86272                  // 64
#define SM_TOT  86336

// ---- k_attn dynamic SMEM layout ----
#define AT_KS   0                      // 256*20*4 = 20480
#define AT_VS   20480                  // 20480
#define AT_PS   40960                  // 16*256*4 = 16384
#define AT_TOT  57344

// ---------------- scratch ----------------
__device__ float g_part[7*BN];
__device__ float g_bias[BB*HH*NN*NN];
__device__ float g_q[BN*DD];
__device__ float g_k[BN*DD];
__device__ float g_v[BN*DD];
__device__ float g_ao[BN*DD];
// pre-split fp16 weights (zero-init; pads stay 0)
__device__ __align__(16) __half g_w1h[64*BSTR];
__device__ __align__(16) __half g_w1l[64*BSTR];
__device__ __align__(16) __half g_w2h[64*BSTR];
__device__ __align__(16) __half g_w2l[64*BSTR];
__device__ __align__(16) __half g_w3h[64*B3STR];
__device__ __align__(16) __half g_w3l[64*B3STR];

// ---------------- helpers ----------------
__device__ __forceinline__ uint32_t smem_u32(const void* p) {
    uint32_t a;
    asm("{ .reg .u64 t; cvta.to.shared.u64 t, %1; cvt.u32.u64 %0, t; }" : "=r"(a) : "l"(p));
    return a;
}
__device__ __forceinline__ void split_h(float a, __half& hi, __half& lo) {
    hi = __float2half_rn(a);
    lo = __float2half_rn(a - __half2float(hi));
}
// fast tanh-based GELU via MUFU.TANH
__device__ __forceinline__ float gelu_t(float x) {
    const float c = 0.7978845608028654f;   // sqrt(2/pi)
    float u = c * fmaf(0.044715f * x, x * x, x);
    float t;
    asm("tanh.approx.f32 %0, %1;" : "=f"(t) : "f"(u));
    return 0.5f * x * (1.0f + t);
}
// pack 8 floats into hi uint4 + lo uint4
__device__ __forceinline__ void pack8(const float* v, uint4& ph, uint4& pl) {
    uint32_t* phu = (uint32_t*)&ph;
    uint32_t* plu = (uint32_t*)&pl;
    #pragma unroll
    for (int q = 0; q < 4; q++) {
        __half2 hh = __floats2half2_rn(v[2*q+0], v[2*q+1]);
        float2 hf = __half22float2(hh);
        __half2 ll = __floats2half2_rn(v[2*q+0] - hf.x, v[2*q+1] - hf.y);
        phu[q] = *(uint32_t*)&hh;
        plu[q] = *(uint32_t*)&ll;
    }
}
// pack 2 floats into hi u32 + lo u32
__device__ __forceinline__ void pack2(float a, float b, uint32_t& ph, uint32_t& pl) {
    __half2 hh = __floats2half2_rn(a, b);
    float2 hf = __half22float2(hh);
    __half2 ll = __floats2half2_rn(a - hf.x, b - hf.y);
    ph = *(uint32_t*)&hh;
    pl = *(uint32_t*)&ll;
}

// mma.m16n8k16 row.col f32 += f16*f16
__device__ __forceinline__ void mma16816(float* c, const uint32_t* a, const uint32_t* b) {
    asm volatile("mma.sync.aligned.m16n8k16.row.col.f32.f16.f16.f32 "
        "{%0,%1,%2,%3}, {%4,%5,%6,%7}, {%8,%9}, {%0,%1,%2,%3};"
        : "+f"(c[0]), "+f"(c[1]), "+f"(c[2]), "+f"(c[3])
        : "r"(a[0]), "r"(a[1]), "r"(a[2]), "r"(a[3]), "r"(b[0]), "r"(b[1]));
}
__device__ __forceinline__ void ldsm_x4(uint32_t* r, uint32_t addr) {
    asm volatile("ldmatrix.sync.aligned.m8n8.x4.shared.b16 {%0,%1,%2,%3}, [%4];"
        : "=r"(r[0]), "=r"(r[1]), "=r"(r[2]), "=r"(r[3]) : "r"(addr));
}
__device__ __forceinline__ void ldsm_x2t(uint32_t* r, uint32_t addr) {
    asm volatile("ldmatrix.sync.aligned.m8n8.x2.trans.shared.b16 {%0,%1}, [%2];"
        : "=r"(r[0]), "=r"(r[1]) : "r"(addr));
}

// ---------------- kernel 0: pre-split the MLP weights ----------------
__global__ void k_wsplit(const float* __restrict__ w1, const float* __restrict__ w2,
                         const float* __restrict__ w3) {
    int t = blockIdx.x * 256 + threadIdx.x;
    if (t < 4096) {
        int k = t >> 6, n = t & 63;
        __half h, l;
        split_h(w1[t], h, l);
        g_w1h[k*BSTR + n] = h; g_w1l[k*BSTR + n] = l;
        split_h(w2[t], h, l);
        g_w2h[k*BSTR + n] = h; g_w2l[k*BSTR + n] = l;
    }
    if (t < 512) {
        int k = t >> 3, n = t & 7;
        __half h, l;
        split_h(w3[k*8 + n], h, l);
        g_w3h[k*B3STR + n] = h; g_w3l[k*B3STR + n] = l;
    }
}

// ---------------- kernel 1: per-particle features ----------------
__global__ void k_part(const float* __restrict__ x_pf) {
    int idx = blockIdx.x * blockDim.x + threadIdx.x;
    if (idx >= BN) return;
    int b = idx >> 8;
    int n = idx & 255;
    const float* base = x_pf + b * 4 * NN + n;
    float px = base[0];
    float py = base[NN];
    float pz = base[2*NN];
    float e  = base[3*NN];
    float pt  = sqrtf(fmaxf(px*px + py*py, EPSF));
    float rap = 0.5f * log1pf(2.0f * pz / fmaxf(e - pz, 1e-20f));
    float phi = atan2f(py, px);
    g_part[0*BN + idx] = px;
    g_part[1*BN + idx] = py;
    g_part[2*BN + idx] = pz;
    g_part[3*BN + idx] = e;
    g_part[4*BN + idx] = pt;
    g_part[5*BN + idx] = rap;
    g_part[6*BN + idx] = phi;
}

// ---------------- kernel 2: pair MLP, register-resident PTX mma ----------------
// Block = 128 threads = 128 pairs. 4 warps, each owns a 32-row M-slab (2 m16 tiles).
// After layer0 handoff via ldmatrix, layers 1-3 stay entirely in registers:
// C fragment of m16n8k16 (two adjacent n8 tiles) == A fragment of the next mma.
__global__ __launch_bounds__(128) void k_pair(
    const float* __restrict__ w0, const float* __restrict__ b0,
    const float* __restrict__ b1, const float* __restrict__ b2,
    const float* __restrict__ b3)
{
    extern __shared__ __align__(16) unsigned char sm[];
    __half* sAh = (__half*)(sm + SM_AH);
    __half* sAl = (__half*)(sm + SM_AL);
    float* sw0 = (float*)(sm + SM_W0);
    float* sb0 = (float*)(sm + SM_SB0);
    float* sb1 = (float*)(sm + SM_SB1);
    float* sb2 = (float*)(sm + SM_SB2);
    float* sb3 = (float*)(sm + SM_SB3);

    int tid = threadIdx.x;
    int warp = tid >> 5;
    int lane = tid & 31;
    uint32_t smem_base = smem_u32(sm);

    // ---- copy pre-split weights (vector copies) ----
    {
        const uint4* s1h = (const uint4*)g_w1h;
        const uint4* s1l = (const uint4*)g_w1l;
        const uint4* s2h = (const uint4*)g_w2h;
        const uint4* s2l = (const uint4*)g_w2l;
        uint4* d1h = (uint4*)(sm + SM_B1H);
        uint4* d1l = (uint4*)(sm + SM_B1L);
        uint4* d2h = (uint4*)(sm + SM_B2H);
        uint4* d2l = (uint4*)(sm + SM_B2L);
        for (int t = tid; t < 576; t += 128) {
            d1h[t] = s1h[t]; d1l[t] = s1l[t];
            d2h[t] = s2h[t]; d2l[t] = s2l[t];
        }
        const uint4* s3h = (const uint4*)g_w3h;
        const uint4* s3l = (const uint4*)g_w3l;
        uint4* d3h = (uint4*)(sm + SM_B3H);
        uint4* d3l = (uint4*)(sm + SM_B3L);
        for (int t = tid; t < 192; t += 128) { d3h[t] = s3h[t]; d3l[t] = s3l[t]; }
    }
    for (int t = tid; t < 256; t += 128) sw0[t] = w0[t];
    if (tid < 64) { sb0[tid] = b0[tid]; sb1[tid] = b1[tid]; sb2[tid] = b2[tid]; }
    if (tid < 8)  sb3[tid] = b3[tid];

    // ---- tile decode ----
    int bid = blockIdx.x;
    int b   = bid / (NTP * 2);
    int rem = bid - b * (NTP * 2);
    int tp  = rem >> 1;
    int jh  = rem & 1;
    int ti = 0;
    while (tp >= NTILE - ti) { tp -= NTILE - ti; ti++; }
    int tj = ti + tp;

    int il = tid >> 3;                  // 0..15
    int jl = tid & 7;                   // 0..7
    int i  = ti * 16 + il;
    int jbase = tj * 16 + jh * 8;
    int j  = jbase + jl;
    int bi = (b << 8) + i;
    int bj = (b << 8) + j;

    // ---- pairwise features ----
    float pxi = g_part[0*BN+bi], pxj = g_part[0*BN+bj];
    float pyi = g_part[1*BN+bi], pyj = g_part[1*BN+bj];
    float pzi = g_part[2*BN+bi], pzj = g_part[2*BN+bj];
    float ei  = g_part[3*BN+bi], ej  = g_part[3*BN+bj];
    float pti = g_part[4*BN+bi], ptj = g_part[4*BN+bj];
    float rpi = g_part[5*BN+bi], rpj = g_part[5*BN+bj];
    float phi_i = g_part[6*BN+bi], phi_j = g_part[6*BN+bj];

    float drap = rpi - rpj;
    float dw = phi_i - phi_j + PI_F;
    dw -= floorf(dw * INV_TWO_PI_F) * TWO_PI_F;
    float dphi = dw - PI_F;
    float delta = sqrtf(drap*drap + dphi*dphi);
    float lndelta = __logf(fmaxf(delta, EPSF));
    float ptmin = fminf(pti, ptj);
    float lnkt = __logf(fmaxf(ptmin * delta, EPSF));
    float lnz  = __logf(fmaxf(__fdividef(ptmin, fmaxf(pti + ptj, EPSF)), EPSF));
    float es = ei + ej, xs = pxi + pxj, ys = pyi + pyj, zs = pzi + pzj;
    float lnm2 = __logf(fmaxf(es*es - xs*xs - ys*ys - zs*zs, EPSF));
    float f0 = lnkt, f1 = lnz, f2 = lndelta, f3 = lnm2;

    __syncthreads();   // weights ready

    // ---- layer 0 (4->64) per-thread fp32 -> gelu -> split fp16 row tid ----
    {
        float act[64];
        #pragma unroll
        for (int c = 0; c < 64; c += 4) {
            float4 a = *(const float4*)&sb0[c];
            float4 w;
            w = *(const float4*)&sw0[0*64 + c];
            a.x = fmaf(f0,w.x,a.x); a.y = fmaf(f0,w.y,a.y); a.z = fmaf(f0,w.z,a.z); a.w = fmaf(f0,w.w,a.w);
            w = *(const float4*)&sw0[1*64 + c];
            a.x = fmaf(f1,w.x,a.x); a.y = fmaf(f1,w.y,a.y); a.z = fmaf(f1,w.z,a.z); a.w = fmaf(f1,w.w,a.w);
            w = *(const float4*)&sw0[2*64 + c];
            a.x = fmaf(f2,w.x,a.x); a.y = fmaf(f2,w.y,a.y); a.z = fmaf(f2,w.z,a.z); a.w = fmaf(f2,w.w,a.w);
            w = *(const float4*)&sw0[3*64 + c];
            a.x = fmaf(f3,w.x,a.x); a.y = fmaf(f3,w.y,a.y); a.z = fmaf(f3,w.z,a.z); a.w = fmaf(f3,w.w,a.w);
            act[c+0] = gelu_t(a.x); act[c+1] = gelu_t(a.y);
            act[c+2] = gelu_t(a.z); act[c+3] = gelu_t(a.w);
        }
        #pragma unroll
        for (int c = 0; c < 64; c += 8) {
            uint4 ph, pl;
            pack8(&act[c], ph, pl);
            *(uint4*)&sAh[tid*ASTR + c] = ph;
            *(uint4*)&sAl[tid*ASTR + c] = pl;
        }
    }
    __syncwarp();      // warp slab complete (warps only read their own rows)

    float* scr = (float*)(sm + SM_SCR) + warp * 288;   // [32 rows][9]

    // ---- layers 1-3 in registers, one m16 tile pair per iteration ----
    #pragma unroll 1
    for (int mt = 0; mt < 2; mt++) {
        int mrow = warp*32 + mt*16;

        // A fragments from layer0 SMEM
        uint32_t Ah[4][4], Al[4][4];
        {
            uint32_t row = (uint32_t)(mrow + (lane & 15));
            uint32_t col = (uint32_t)((lane >> 4) << 3);
            uint32_t off = (row*ASTR + col) * 2;
            #pragma unroll
            for (int kt = 0; kt < 4; kt++) {
                ldsm_x4(Ah[kt], smem_base + SM_AH + off + kt*32);
                ldsm_x4(Al[kt], smem_base + SM_AL + off + kt*32);
            }
        }

        // layers 1 & 2
        #pragma unroll 1
        for (int layer = 0; layer < 2; layer++) {
            uint32_t boff = (layer == 0) ? SM_B1H : SM_B2H;
            const float* bias = (layer == 0) ? sb1 : sb2;

            float C[8][4];
            #pragma unroll
            for (int nt = 0; nt < 8; nt++)
                #pragma unroll
                for (int q = 0; q < 4; q++) C[nt][q] = 0.0f;

            uint32_t brow_off = ((uint32_t)(lane & 15) * BSTR) * 2;
            #pragma unroll
            for (int kt = 0; kt < 4; kt++) {
                uint32_t kaddr = smem_base + boff + kt*16*BSTR*2 + brow_off;
                #pragma unroll
                for (int nt = 0; nt < 8; nt++) {
                    uint32_t bh[2], bl[2];
                    ldsm_x2t(bh, kaddr + nt*16);
                    ldsm_x2t(bl, kaddr + nt*16 + 9216);
                    mma16816(C[nt], Ah[kt], bh);
                    mma16816(C[nt], Ah[kt], bl);
                    mma16816(C[nt], Al[kt], bh);
                }
            }

            // bias + gelu + split-pack: C tiles (2k2, 2k2+1) -> A fragment k-tile k2
            int cb = (lane & 3) * 2;
            #pragma unroll
            for (int k2 = 0; k2 < 4; k2++) {
                float be0 = bias[(2*k2)*8 + cb],     bo0 = bias[(2*k2)*8 + cb + 1];
                float be1 = bias[(2*k2+1)*8 + cb],   bo1 = bias[(2*k2+1)*8 + cb + 1];
                float g0 = gelu_t(C[2*k2][0] + be0);
                float g1 = gelu_t(C[2*k2][1] + bo0);
                float g2 = gelu_t(C[2*k2][2] + be0);
                float g3 = gelu_t(C[2*k2][3] + bo0);
                float g4 = gelu_t(C[2*k2+1][0] + be1);
                float g5 = gelu_t(C[2*k2+1][1] + bo1);
                float g6 = gelu_t(C[2*k2+1][2] + be1);
                float g7 = gelu_t(C[2*k2+1][3] + bo1);
                pack2(g0, g1, Ah[k2][0], Al[k2][0]);
                pack2(g2, g3, Ah[k2][1], Al[k2][1]);
                pack2(g4, g5, Ah[k2][2], Al[k2][2]);
                pack2(g6, g7, Ah[k2][3], Al[k2][3]);
            }
        }

        // layer 3: 64 -> 8 (single n8 tile)
        {
            float C3[4] = {0.f, 0.f, 0.f, 0.f};
            uint32_t brow_off = ((uint32_t)(lane & 15) * B3STR) * 2;
            #pragma unroll
            for (int kt = 0; kt < 4; kt++) {
                uint32_t kaddr = smem_base + SM_B3H + kt*16*B3STR*2 + brow_off;
                uint32_t bh[2], bl[2];
                ldsm_x2t(bh, kaddr);
                ldsm_x2t(bl, kaddr + 3072);
                mma16816(C3, Ah[kt], bh);
                mma16816(C3, Ah[kt], bl);
                mma16816(C3, Al[kt], bh);
            }
            int g = lane >> 2;
            int h0 = (lane & 3) * 2;
            int r0 = mt*16 + g;
            scr[(r0    )*9 + h0    ] = C3[0] + sb3[h0];
            scr[(r0    )*9 + h0 + 1] = C3[1] + sb3[h0+1];
            scr[(r0 + 8)*9 + h0    ] = C3[2] + sb3[h0];
            scr[(r0 + 8)*9 + h0 + 1] = C3[3] + sb3[h0+1];
        }
    }
    __syncwarp();

    // each thread picks up its own pair's 8 outputs
    float outv[8];
    #pragma unroll
    for (int h = 0; h < 8; h++) outv[h] = scr[lane*9 + h];

    // ---- direct write [b,h,i,j] ----
    #pragma unroll
    for (int h = 0; h < 8; h++)
        g_bias[(((b*8 + h)*256 + i))*256 + j] = outv[h];

    // ---- mirror write [b,h,j,i] via staging (reuse B1H region) ----
    __syncthreads();
    float* st = (float*)(sm + SM_B1H);     // [8][8][18] floats = 4608B
    #pragma unroll
    for (int h = 0; h < 8; h++) st[(h*8 + jl)*18 + il] = outv[h];
    __syncthreads();
    for (int t = tid; t < 256; t += 128) {
        int h = t >> 5, r = t & 31, jl2 = r >> 2, iq = r & 3;
        const float* s = &st[(h*8 + jl2)*18 + iq*4];
        float4 v = make_float4(s[0], s[1], s[2], s[3]);
        int jrow = jbase + jl2;
        float* q = g_bias + (((b*8 + h)*256 + jrow))*256 + ti*16 + iq*4;
        *(float4*)q = v;
    }
}

// ---------------- kernel 3: QKV projections (8 rows/block, grid 512) ----------------
__global__ __launch_bounds__(128) void k_qkv(
    const float* __restrict__ xf,
    const float* __restrict__ wq, const float* __restrict__ wk, const float* __restrict__ wv,
    const float* __restrict__ bq, const float* __restrict__ bk, const float* __restrict__ bv)
{
    __shared__ float xs[8][128];
    int tid = threadIdx.x;
    int r0 = blockIdx.x * 8;
    for (int t = tid; t < 8*128; t += 128) xs[t >> 7][t & 127] = xf[r0*128 + t];
    __syncthreads();

    int d = tid;
    float aq[8], ak[8], av[8];
    float bqv = bq[d], bkv = bk[d], bvv = bv[d];
    #pragma unroll
    for (int r = 0; r < 8; r++) { aq[r] = bqv; ak[r] = bkv; av[r] = bvv; }

    #pragma unroll 8
    for (int k = 0; k < 128; k++) {
        float wqv = wq[k*128 + d];
        float wkv = wk[k*128 + d];
        float wvv = wv[k*128 + d];
        #pragma unroll
        for (int r = 0; r < 8; r++) {
            float x = xs[r][k];
            aq[r] = fmaf(x, wqv, aq[r]);
            ak[r] = fmaf(x, wkv, ak[r]);
            av[r] = fmaf(x, wvv, av[r]);
        }
    }
    #pragma unroll
    for (int r = 0; r < 8; r++) {
        int row = r0 + r;
        g_q[row*128 + d] = aq[r];
        g_k[row*128 + d] = ak[r];
        g_v[row*128 + d] = av[r];
    }
}

// ---------------- kernel 4: attention, 2 rows per warp, 32 rows per block ----------------
__global__ __launch_bounds__(256, 2) void k_attn() {
    extern __shared__ __align__(16) unsigned char smd[];
    float (*ks)[20] = (float(*)[20])(smd + AT_KS);
    float (*vs)[20] = (float(*)[20])(smd + AT_VS);
    float (*ps)[256] = (float(*)[256])(smd + AT_PS);

    int bid = blockIdx.x;          // grid = 16*8*8 = 1024
    int it = bid & 7;              // 32-row tile
    int h  = (bid >> 3) & 7;
    int b  = bid >> 6;

    int tid = threadIdx.x;
    {
        int j = tid;
        const float* kp = g_k + (b*256 + j)*128 + h*16;
        const float* vp = g_v + (b*256 + j)*128 + h*16;
        #pragma unroll
        for (int d = 0; d < 16; d += 4) {
            *(float4*)&ks[j][d] = *(const float4*)&kp[d];
            *(float4*)&vs[j][d] = *(const float4*)&vp[d];
        }
    }
    __syncthreads();

    int w = tid >> 5;
    int lane = tid & 31;

    #pragma unroll 1
    for (int pr = 0; pr < 2; pr++) {
        int i0 = it*32 + w*4 + pr*2;           // rows i0, i0+1

        const float* qp0 = g_q + (b*256 + i0)*128 + h*16;
        float q0[16], q1[16];
        #pragma unroll
        for (int d = 0; d < 16; d++) { q0[d] = qp0[d]; q1[d] = qp0[128 + d]; }

        const float* bp0 = g_bias + ((b*8 + h)*256 + i0)*256;
        float bb0[8], bb1[8];
        #pragma unroll
        for (int jj = 0; jj < 8; jj++) {
            bb0[jj] = bp0[jj*32 + lane];
            bb1[jj] = bp0[256 + jj*32 + lane];
        }

        float s0[8], s1[8];
        float m0 = -1e30f, m1 = -1e30f;
        #pragma unroll
        for (int jj = 0; jj < 8; jj++) {
            int j = jj*32 + lane;
            float4 k0 = *(const float4*)&ks[j][0];
            float4 k1 = *(const float4*)&ks[j][4];
            float4 k2 = *(const float4*)&ks[j][8];
            float4 k3 = *(const float4*)&ks[j][12];
            float e0 = q0[0]*k0.x;
            e0 = fmaf(q0[1],k0.y,e0); e0 = fmaf(q0[2],k0.z,e0); e0 = fmaf(q0[3],k0.w,e0);
            e0 = fmaf(q0[4],k1.x,e0); e0 = fmaf(q0[5],k1.y,e0); e0 = fmaf(q0[6],k1.z,e0); e0 = fmaf(q0[7],k1.w,e0);
            float e1 = q0[8]*k2.x;
            e1 = fmaf(q0[9],k2.y,e1);  e1 = fmaf(q0[10],k2.z,e1); e1 = fmaf(q0[11],k2.w,e1);
            e1 = fmaf(q0[12],k3.x,e1); e1 = fmaf(q0[13],k3.y,e1); e1 = fmaf(q0[14],k3.z,e1); e1 = fmaf(q0[15],k3.w,e1);
            s0[jj] = (e0 + e1) * 0.25f + bb0[jj];
            m0 = fmaxf(m0, s0[jj]);
            float f0 = q1[0]*k0.x;
            f0 = fmaf(q1[1],k0.y,f0); f0 = fmaf(q1[2],k0.z,f0); f0 = fmaf(q1[3],k0.w,f0);
            f0 = fmaf(q1[4],k1.x,f0); f0 = fmaf(q1[5],k1.y,f0); f0 = fmaf(q1[6],k1.z,f0); f0 = fmaf(q1[7],k1.w,f0);
            float f1 = q1[8]*k2.x;
            f1 = fmaf(q1[9],k2.y,f1);  f1 = fmaf(q1[10],k2.z,f1); f1 = fmaf(q1[11],k2.w,f1);
            f1 = fmaf(q1[12],k3.x,f1); f1 = fmaf(q1[13],k3.y,f1); f1 = fmaf(q1[14],k3.z,f1); f1 = fmaf(q1[15],k3.w,f1);
            s1[jj] = (f0 + f1) * 0.25f + bb1[jj];
            m1 = fmaxf(m1, s1[jj]);
        }
        #pragma unroll
        for (int off = 16; off >= 1; off >>= 1) {
            m0 = fmaxf(m0, __shfl_xor_sync(0xffffffffu, m0, off));
            m1 = fmaxf(m1, __shfl_xor_sync(0xffffffffu, m1, off));
        }
        float sum0 = 0.0f, sum1 = 0.0f;
        #pragma unroll
        for (int jj = 0; jj < 8; jj++) {
            s0[jj] = __expf(s0[jj] - m0); sum0 += s0[jj];
            s1[jj] = __expf(s1[jj] - m1); sum1 += s1[jj];
        }
        #pragma unroll
        for (int off = 16; off >= 1; off >>= 1) {
            sum0 += __shfl_xor_sync(0xffffffffu, sum0, off);
            sum1 += __shfl_xor_sync(0xffffffffu, sum1, off);
        }
        float inv0 = __fdividef(1.0f, sum0);
        float inv1 = __fdividef(1.0f, sum1);

        int sl0 = w*2, sl1 = w*2 + 1;
        #pragma unroll
        for (int jj = 0; jj < 8; jj++) {
            ps[sl0][jj*32 + lane] = s0[jj] * inv0;
            ps[sl1][jj*32 + lane] = s1[jj] * inv1;
        }
        __syncwarp();

        {
            int d4 = lane & 3;
            int jp = lane >> 2;
            float4 a0 = make_float4(0.f,0.f,0.f,0.f);
            float4 a1 = make_float4(0.f,0.f,0.f,0.f);
            #pragma unroll 4
            for (int jj = 0; jj < 32; jj++) {
                int j = jj*8 + jp;
                float4 v = *(const float4*)&vs[j][d4*4];
                float p0 = ps[sl0][j];
                float p1 = ps[sl1][j];
                a0.x = fmaf(p0, v.x, a0.x); a0.y = fmaf(p0, v.y, a0.y);
                a0.z = fmaf(p0, v.z, a0.z); a0.w = fmaf(p0, v.w, a0.w);
                a1.x = fmaf(p1, v.x, a1.x); a1.y = fmaf(p1, v.y, a1.y);
                a1.z = fmaf(p1, v.z, a1.z); a1.w = fmaf(p1, v.w, a1.w);
            }
            #pragma unroll
            for (int off = 4; off <= 16; off <<= 1) {
                a0.x += __shfl_xor_sync(0xffffffffu, a0.x, off);
                a0.y += __shfl_xor_sync(0xffffffffu, a0.y, off);
                a0.z += __shfl_xor_sync(0xffffffffu, a0.z, off);
                a0.w += __shfl_xor_sync(0xffffffffu, a0.w, off);
                a1.x += __shfl_xor_sync(0xffffffffu, a1.x, off);
                a1.y += __shfl_xor_sync(0xffffffffu, a1.y, off);
                a1.z += __shfl_xor_sync(0xffffffffu, a1.z, off);
                a1.w += __shfl_xor_sync(0xffffffffu, a1.w, off);
            }
            if (jp == 0) {
                *(float4*)&g_ao[(b*256 + i0)*128 + h*16 + d4*4] = a0;
                *(float4*)&g_ao[(b*256 + i0 + 1)*128 + h*16 + d4*4] = a1;
            }
        }
        __syncwarp();
    }
}

// ---------------- kernel 5: output projection (8 rows/block, grid 512) ----------------
__global__ __launch_bounds__(128) void k_outproj(
    const float* __restrict__ wo, const float* __restrict__ bo, float* __restrict__ out)
{
    __shared__ float xs[8][128];
    int tid = threadIdx.x;
    int r0 = blockIdx.x * 8;
    for (int t = tid; t < 8*128; t += 128) xs[t >> 7][t & 127] = g_ao[r0*128 + t];
    __syncthreads();

    int d = tid;
    float acc[8];
    float bv = bo[d];
    #pragma unroll
    for (int r = 0; r < 8; r++) acc[r] = bv;

    #pragma unroll 8
    for (int k = 0; k < 128; k++) {
        float wv = wo[k*128 + d];
        #pragma unroll
        for (int r = 0; r < 8; r++) acc[r] = fmaf(xs[r][k], wv, acc[r]);
    }
    #pragma unroll
    for (int r = 0; r < 8; r++) out[(r0 + r)*128 + d] = acc[r];
}

// ---------------- launch ----------------
extern "C" void kernel_launch(void* const* d_in, const int* in_sizes, int n_in,
                              void* d_out, int out_size) {
    (void)in_sizes; (void)n_in; (void)out_size;
    const float* x_pf   = (const float*)d_in[0];
    const float* x_feat = (const float*)d_in[1];
    const float* w0 = (const float*)d_in[2];
    const float* b0 = (const float*)d_in[3];
    const float* w1 = (const float*)d_in[4];
    const float* b1 = (const float*)d_in[5];
    const float* w2 = (const float*)d_in[6];
    const float* b2 = (const float*)d_in[7];
    const float* w3 = (const float*)d_in[8];
    const float* b3 = (const float*)d_in[9];
    const float* wq = (const float*)d_in[10];
    const float* wk = (const float*)d_in[11];
    const float* wv = (const float*)d_in[12];
    const float* wo = (const float*)d_in[13];
    const float* bq = (const float*)d_in[14];
    const float* bk = (const float*)d_in[15];
    const float* bv = (const float*)d_in[16];
    const float* bo = (const float*)d_in[17];

    cudaFuncSetAttribute(k_pair, cudaFuncAttributeMaxDynamicSharedMemorySize, SM_TOT);
    cudaFuncSetAttribute(k_attn, cudaFuncAttributeMaxDynamicSharedMemorySize, AT_TOT);

    k_wsplit<<<16, 256>>>(w1, w2, w3);
    k_part<<<16, 256>>>(x_pf);
    k_pair<<<BB*NTP*2, 128, SM_TOT>>>(w0, b0, b1, b2, b3);
    k_qkv<<<512, 128>>>(x_feat, wq, wk, wv, bq, bk, bv);
    k_attn<<<1024, 256, AT_TOT>>>();
    k_outproj<<<512, 128>>>(wo, bo, (float*)d_out);
}